// round 1
// baseline (speedup 1.0000x reference)
#include <cuda_runtime.h>
#include <math.h>

#define DM 512
#define TT 1024
#define BB 2
#define NH 8
#define BH 16      // BB*NH
#define CH 64      // chunk length
#define NCH 16     // TT/CH

// ---------------- scratch (device globals; no allocations) ----------------
__device__ float g_s[4];                    // ternary scale per matrix
__device__ float g_si[4];                   // 1/s (exact, power of two)
__device__ float g_phiQ[BH*TT*64];          // (b,h,t,d)
__device__ float g_phiK[BH*TT*64];
__device__ float g_V  [BH*TT*64];
__device__ float g_kv [BH*NCH*64*64];       // per-chunk K^T V sums -> exclusive prefix
__device__ float g_ks [BH*NCH*64];          // per-chunk K colsums  -> exclusive prefix
__device__ float g_attn[BB*TT*DM];          // attention output, (b,t,e)

// ---------------- 1) ternary scales ----------------
__global__ void scales_kernel(const float* __restrict__ Wq, const float* __restrict__ Wk,
                              const float* __restrict__ Wv, const float* __restrict__ Wo)
{
    const float* W = blockIdx.x==0?Wq: blockIdx.x==1?Wk: blockIdx.x==2?Wv:Wo;
    __shared__ float red[256];
    float a = 0.f;
    for (int i = threadIdx.x; i < DM*DM; i += 256) a += fabsf(W[i]);
    red[threadIdx.x] = a; __syncthreads();
    for (int o = 128; o > 0; o >>= 1) {
        if (threadIdx.x < o) red[threadIdx.x] += red[threadIdx.x + o];
        __syncthreads();
    }
    if (threadIdx.x == 0) {
        float alpha = red[0] * (1.0f/(DM*DM)) + 1e-12f;   // /2^18 exact
        float e = rintf(log2f(alpha));
        e = fminf(fmaxf(e, -4.f), 4.f);
        g_s [blockIdx.x] = exp2f(e);
        g_si[blockIdx.x] = exp2f(-e);
    }
}

// ---------------- 2) GEMM (shared for QKV+phi and output projection) ----------------
// y[m,n] = sum_k A[m,k] * tern(W[n,k]);  mode 0: A=x, W in {Wq,Wk,Wv} by n-range,
// epilogue = phi (for Q,K) + scatter to (b,h,t,d).   mode 1: A=g_attn, W=Wo, +bias -> d_out.
__global__ __launch_bounds__(256) void gemm_kernel(
    const float* __restrict__ Ain,
    const float* __restrict__ W0, const float* __restrict__ W1, const float* __restrict__ W2,
    const float* __restrict__ bias, const float* __restrict__ phi_table,
    float* __restrict__ Out, int mode)
{
    __shared__ float As[16][65];
    __shared__ float Bs[16][65];
    __shared__ float tbl[512];

    const int tid = threadIdx.x;
    if (mode == 0) { tbl[tid] = phi_table[tid]; tbl[tid+256] = phi_table[tid+256]; }

    const float* A = (mode == 1) ? g_attn : Ain;
    const int m0 = blockIdx.y * 64;
    const int n0 = blockIdx.x * 64;
    const int mat = (mode == 0) ? (n0 >> 9) : 3;
    const float* W = (mat==0)?W0 : (mat==1)?W1 : (mat==2)?W2 : W0;  // mode1 passes Wo as W0
    const int nb = (mode == 0) ? (n0 & 511) : n0;
    const float s  = g_s [mat];
    const float si = g_si[mat];

    const int lr = tid >> 2;            // 0..63 row within tile
    const int lk = (tid & 3) << 2;      // 0,4,8,12 k-offset
    const int ty = tid >> 4;            // 0..15
    const int tx = tid & 15;            // 0..15

    const float* Aptr = A + (m0 + lr) * DM + lk;
    const float* Wptr = W + (nb + lr) * DM + lk;

    float acc[4][4] = {};

    for (int k0 = 0; k0 < DM; k0 += 16) {
        float4 av = *(const float4*)(Aptr + k0);
        float4 wv = *(const float4*)(Wptr + k0);
        As[lk+0][lr]=av.x; As[lk+1][lr]=av.y; As[lk+2][lr]=av.z; As[lk+3][lr]=av.w;
        // ternary quantize on the fly (exact: si is a power of two)
        Bs[lk+0][lr] = fminf(fmaxf(rintf(wv.x*si),-1.f),1.f)*s;
        Bs[lk+1][lr] = fminf(fmaxf(rintf(wv.y*si),-1.f),1.f)*s;
        Bs[lk+2][lr] = fminf(fmaxf(rintf(wv.z*si),-1.f),1.f)*s;
        Bs[lk+3][lr] = fminf(fmaxf(rintf(wv.w*si),-1.f),1.f)*s;
        __syncthreads();
        #pragma unroll
        for (int k = 0; k < 16; k++) {
            float a0=As[k][ty*4+0], a1=As[k][ty*4+1], a2=As[k][ty*4+2], a3=As[k][ty*4+3];
            float b0=Bs[k][tx*4+0], b1=Bs[k][tx*4+1], b2=Bs[k][tx*4+2], b3=Bs[k][tx*4+3];
            acc[0][0]+=a0*b0; acc[0][1]+=a0*b1; acc[0][2]+=a0*b2; acc[0][3]+=a0*b3;
            acc[1][0]+=a1*b0; acc[1][1]+=a1*b1; acc[1][2]+=a1*b2; acc[1][3]+=a1*b3;
            acc[2][0]+=a2*b0; acc[2][1]+=a2*b1; acc[2][2]+=a2*b2; acc[2][3]+=a2*b3;
            acc[3][0]+=a3*b0; acc[3][1]+=a3*b1; acc[3][2]+=a3*b2; acc[3][3]+=a3*b3;
        }
        __syncthreads();
    }

    if (mode == 0) {
        float* dst = (mat==0) ? g_phiQ : (mat==1) ? g_phiK : g_V;
        #pragma unroll
        for (int r = 0; r < 4; r++) {
            int m = m0 + ty*4 + r;
            int b = m >> 10, t = m & 1023;
            #pragma unroll
            for (int c = 0; c < 4; c++) {
                int nl = nb + tx*4 + c;
                int h = nl >> 6, d = nl & 63;
                float v = acc[r][c];
                if (mat < 2) {
                    // phi: table[0][round(v/0.1)+128] + table[1][round(v/0.2)+128]
                    int i0 = (int)rintf(__fdiv_rn(v, 0.1f)) + 128;
                    int i1 = (int)rintf(__fdiv_rn(v, 0.2f)) + 128;
                    i0 = min(max(i0, 0), 255);
                    i1 = min(max(i1, 0), 255);
                    v = tbl[i0] + tbl[256 + i1];
                }
                dst[(((b<<3) + h) * 1024 + t) * 64 + d] = v;
            }
        }
    } else {
        #pragma unroll
        for (int r = 0; r < 4; r++) {
            int m = m0 + ty*4 + r;
            #pragma unroll
            for (int c = 0; c < 4; c++) {
                int n = n0 + tx*4 + c;
                Out[m*DM + n] = acc[r][c] + bias[n];
            }
        }
    }
}

// ---------------- 3) per-chunk K^T V and K colsum ----------------
__global__ __launch_bounds__(256) void chunksum_kernel()
{
    const int chunk = blockIdx.x, bh = blockIdx.y;
    __shared__ float Kt[CH*64];
    __shared__ float Vt[CH*64];
    const int tid = threadIdx.x;
    const float* Kg = g_phiK + (bh*TT + chunk*CH) * 64;
    const float* Vg = g_V    + (bh*TT + chunk*CH) * 64;
    for (int i = tid; i < CH*16; i += 256) {
        ((float4*)Kt)[i] = ((const float4*)Kg)[i];
        ((float4*)Vt)[i] = ((const float4*)Vg)[i];
    }
    __syncthreads();
    const int d0 = (tid >> 4) * 4, e0 = (tid & 15) * 4;
    float acc[4][4] = {};
    for (int t = 0; t < CH; t++) {
        float a0=Kt[t*64+d0+0], a1=Kt[t*64+d0+1], a2=Kt[t*64+d0+2], a3=Kt[t*64+d0+3];
        float b0=Vt[t*64+e0+0], b1=Vt[t*64+e0+1], b2=Vt[t*64+e0+2], b3=Vt[t*64+e0+3];
        acc[0][0]+=a0*b0; acc[0][1]+=a0*b1; acc[0][2]+=a0*b2; acc[0][3]+=a0*b3;
        acc[1][0]+=a1*b0; acc[1][1]+=a1*b1; acc[1][2]+=a1*b2; acc[1][3]+=a1*b3;
        acc[2][0]+=a2*b0; acc[2][1]+=a2*b1; acc[2][2]+=a2*b2; acc[2][3]+=a2*b3;
        acc[3][0]+=a3*b0; acc[3][1]+=a3*b1; acc[3][2]+=a3*b2; acc[3][3]+=a3*b3;
    }
    float* kvo = g_kv + (bh*NCH + chunk) * 4096;
    #pragma unroll
    for (int r = 0; r < 4; r++)
        #pragma unroll
        for (int c = 0; c < 4; c++)
            kvo[(d0+r)*64 + e0+c] = acc[r][c];
    if (tid < 64) {
        float su = 0.f;
        for (int t = 0; t < CH; t++) su += Kt[t*64 + tid];
        g_ks[(bh*NCH + chunk)*64 + tid] = su;
    }
}

// ---------------- 4) exclusive prefix over chunks (in place) ----------------
__global__ void prefix_kernel()
{
    const int bh = blockIdx.y;
    const int e = blockIdx.x * 256 + threadIdx.x;
    if (e < 4096) {
        float run = 0.f;
        float* base = g_kv + bh*NCH*4096 + e;
        #pragma unroll
        for (int c = 0; c < NCH; c++) { float v = base[c*4096]; base[c*4096] = run; run += v; }
    } else if (e < 4096 + 64) {
        const int d = e - 4096;
        float run = 0.f;
        float* base = g_ks + bh*NCH*64 + d;
        #pragma unroll
        for (int c = 0; c < NCH; c++) { float v = base[c*64]; base[c*64] = run; run += v; }
    }
}

// ---------------- 5) chunked causal attention output ----------------
// dyn smem: Qb[64*64] | Kb[64*65] | Sb[64*64]   (49408 B)
extern __shared__ float dsm[];
__global__ __launch_bounds__(256) void attn_kernel()
{
    const int chunk = blockIdx.x, bh = blockIdx.y;
    float* Qb = dsm;
    float* Kb = dsm + 64*64;
    float* Sb = dsm + 64*64 + 64*65;
    const int tid = threadIdx.x;

    const float* Qg = g_phiQ + (bh*TT + chunk*CH) * 64;
    const float* Kg = g_phiK + (bh*TT + chunk*CH) * 64;
    for (int i = tid; i < 1024; i += 256) ((float4*)Qb)[i] = ((const float4*)Qg)[i];
    for (int i = tid; i < 1024; i += 256) {
        int r = i >> 4, cc = (i & 15) << 2;
        float4 v = ((const float4*)Kg)[i];
        Kb[r*65+cc+0]=v.x; Kb[r*65+cc+1]=v.y; Kb[r*65+cc+2]=v.z; Kb[r*65+cc+3]=v.w;
    }
    __syncthreads();

    const int g1 = tid >> 4, g2 = tid & 15;
    const int i0 = g1 * 4;

    // phase 1: S = phiQ @ phiK^T  (64x64)
    {
        const int j0 = g2 * 4;
        float sacc[4][4] = {};
        for (int d = 0; d < 64; d++) {
            float a0=Qb[(i0+0)*64+d], a1=Qb[(i0+1)*64+d], a2=Qb[(i0+2)*64+d], a3=Qb[(i0+3)*64+d];
            float b0=Kb[(j0+0)*65+d], b1=Kb[(j0+1)*65+d], b2=Kb[(j0+2)*65+d], b3=Kb[(j0+3)*65+d];
            sacc[0][0]+=a0*b0; sacc[0][1]+=a0*b1; sacc[0][2]+=a0*b2; sacc[0][3]+=a0*b3;
            sacc[1][0]+=a1*b0; sacc[1][1]+=a1*b1; sacc[1][2]+=a1*b2; sacc[1][3]+=a1*b3;
            sacc[2][0]+=a2*b0; sacc[2][1]+=a2*b1; sacc[2][2]+=a2*b2; sacc[2][3]+=a2*b3;
            sacc[3][0]+=a3*b0; sacc[3][1]+=a3*b1; sacc[3][2]+=a3*b2; sacc[3][3]+=a3*b3;
        }
        #pragma unroll
        for (int r = 0; r < 4; r++)
            #pragma unroll
            for (int c = 0; c < 4; c++)
                Sb[(i0+r)*64 + j0+c] = sacc[r][c];
    }
    __syncthreads();

    // overwrite Kb with V
    {
        const float* Vg = g_V + (bh*TT + chunk*CH) * 64;
        for (int i = tid; i < 1024; i += 256) {
            int r = i >> 4, cc = (i & 15) << 2;
            float4 v = ((const float4*)Vg)[i];
            Kb[r*65+cc+0]=v.x; Kb[r*65+cc+1]=v.y; Kb[r*65+cc+2]=v.z; Kb[r*65+cc+3]=v.w;
        }
    }
    __syncthreads();

    // phase 2: acc = tril(S) @ V
    const int e0 = g2 * 4;
    float acc[4][4] = {};
    for (int j = 0; j < 64; j++) {
        float b0=Kb[j*65+e0+0], b1=Kb[j*65+e0+1], b2=Kb[j*65+e0+2], b3=Kb[j*65+e0+3];
        #pragma unroll
        for (int r = 0; r < 4; r++) {
            float sv = (j <= i0 + r) ? Sb[(i0+r)*64 + j] : 0.f;
            acc[r][0]+=sv*b0; acc[r][1]+=sv*b1; acc[r][2]+=sv*b2; acc[r][3]+=sv*b3;
        }
    }
    __syncthreads();

    // z-pass (threads 0..63) runs while all threads reload Kb with the prefix state
    const float* stg = g_kv + (bh*NCH + chunk) * 4096;
    const float* ksg = g_ks + (bh*NCH + chunk) * 64;
    float zreg = 0.f;
    if (tid < 64) {
        const int i = tid;
        for (int j = 0; j <= i; j++) zreg += Sb[i*64 + j];
        for (int d = 0; d < 64; d++) zreg += Qb[i*64 + d] * ksg[d];
    }
    for (int i = tid; i < 1024; i += 256) {
        int r = i >> 4, cc = (i & 15) << 2;
        float4 v = ((const float4*)stg)[i];
        Kb[r*65+cc+0]=v.x; Kb[r*65+cc+1]=v.y; Kb[r*65+cc+2]=v.z; Kb[r*65+cc+3]=v.w;
    }
    if (tid < 64) Sb[tid] = zreg;   // stash Z in row 0 of Sb (not read by anyone else now)
    __syncthreads();

    // phase 3: acc += phiQ @ state
    for (int d = 0; d < 64; d++) {
        float b0=Kb[d*65+e0+0], b1=Kb[d*65+e0+1], b2=Kb[d*65+e0+2], b3=Kb[d*65+e0+3];
        float a0=Qb[(i0+0)*64+d], a1=Qb[(i0+1)*64+d], a2=Qb[(i0+2)*64+d], a3=Qb[(i0+3)*64+d];
        acc[0][0]+=a0*b0; acc[0][1]+=a0*b1; acc[0][2]+=a0*b2; acc[0][3]+=a0*b3;
        acc[1][0]+=a1*b0; acc[1][1]+=a1*b1; acc[1][2]+=a1*b2; acc[1][3]+=a1*b3;
        acc[2][0]+=a2*b0; acc[2][1]+=a2*b1; acc[2][2]+=a2*b2; acc[2][3]+=a2*b3;
        acc[3][0]+=a3*b0; acc[3][1]+=a3*b1; acc[3][2]+=a3*b2; acc[3][3]+=a3*b3;
    }

    // write out, normalized: (b, t, h*64+e)
    const int b = bh >> 3, h = bh & 7;
    #pragma unroll
    for (int r = 0; r < 4; r++) {
        const int t = chunk*CH + i0 + r;
        const float z = fmaxf(Sb[i0 + r], 1e-6f);
        float4 o;
        o.x = __fdiv_rn(acc[r][0], z);
        o.y = __fdiv_rn(acc[r][1], z);
        o.z = __fdiv_rn(acc[r][2], z);
        o.w = __fdiv_rn(acc[r][3], z);
        *(float4*)(g_attn + (b*TT + t)*DM + h*64 + e0) = o;
    }
}

// ---------------- launch ----------------
extern "C" void kernel_launch(void* const* d_in, const int* in_sizes, int n_in,
                              void* d_out, int out_size)
{
    const float* x   = (const float*)d_in[0];
    const float* Wq  = (const float*)d_in[1];
    const float* Wk  = (const float*)d_in[2];
    const float* Wv  = (const float*)d_in[3];
    const float* Wo  = (const float*)d_in[4];
    const float* bo  = (const float*)d_in[5];
    const float* phi = (const float*)d_in[6];
    float* out = (float*)d_out;

    const int attn_smem = (64*64 + 64*65 + 64*64) * sizeof(float); // 49408
    cudaFuncSetAttribute(attn_kernel, cudaFuncAttributeMaxDynamicSharedMemorySize, attn_smem);

    scales_kernel<<<4, 256>>>(Wq, Wk, Wv, Wo);
    gemm_kernel<<<dim3(24, 32), 256>>>(x, Wq, Wk, Wv, nullptr, phi, nullptr, 0);
    chunksum_kernel<<<dim3(NCH, BH), 256>>>();
    prefix_kernel<<<dim3(17, BH), 256>>>();
    attn_kernel<<<dim3(NCH, BH), 256, attn_smem>>>();
    gemm_kernel<<<dim3(8, 32), 256>>>(x, Wo, nullptr, nullptr, bo, nullptr, out, 1);
}

// round 3
// speedup vs baseline: 1.5993x; 1.5993x over previous
#include <cuda_runtime.h>
#include <cuda_bf16.h>
#include <math.h>
#include <stdint.h>

#define DM 512
#define TT 1024
#define BB 2
#define NH 8
#define BH 16      // BB*NH
#define CH 64      // chunk length
#define NCH 16     // TT/CH

// ---------------- scratch (device globals; no allocations) ----------------
__device__ float g_s[4];
__device__ float g_si[4];
__device__ float g_phiQ[BH*TT*64];          // (b,h,t,d)
__device__ float g_phiK[BH*TT*64];
__device__ float g_V  [BH*TT*64];
__device__ float g_kv [BH*NCH*64*64];
__device__ float g_ks [BH*NCH*64];
__device__ float g_attn[BB*TT*DM];          // (b,t,e)
__device__ __nv_bfloat16 g_wt[4*512*512];   // ternary weights in bf16 (exact), [mat][n][k]
__device__ __nv_bfloat16 g_xs[3*2048*512];  // 3-way bf16 split of x
__device__ __nv_bfloat16 g_as[3*2048*512];  // 3-way bf16 split of attn out

// byte-offset swizzle within a 128B row (Swizzle<3,4,3>)
#define SWZ(o) ((o) ^ ((((o) >> 7) & 7) << 4))

__device__ __forceinline__ uint32_t smem_u32(const void* p) {
    uint32_t a;
    asm("{ .reg .u64 t; cvta.to.shared.u64 t, %1; cvt.u32.u64 %0, t; }" : "=r"(a) : "l"(p));
    return a;
}
__device__ __forceinline__ void ldmx4(uint32_t* r, uint32_t addr) {
    asm volatile("ldmatrix.sync.aligned.m8n8.x4.shared.b16 {%0,%1,%2,%3}, [%4];"
                 : "=r"(r[0]), "=r"(r[1]), "=r"(r[2]), "=r"(r[3]) : "r"(addr));
}
__device__ __forceinline__ void ldmx2(uint32_t* r, uint32_t addr) {
    asm volatile("ldmatrix.sync.aligned.m8n8.x2.shared.b16 {%0,%1}, [%2];"
                 : "=r"(r[0]), "=r"(r[1]) : "r"(addr));
}
__device__ __forceinline__ void mma16816(float* c, const uint32_t* a, const uint32_t* b) {
    asm volatile("mma.sync.aligned.m16n8k16.row.col.f32.bf16.bf16.f32 "
                 "{%0,%1,%2,%3},{%4,%5,%6,%7},{%8,%9},{%0,%1,%2,%3};"
                 : "+f"(c[0]), "+f"(c[1]), "+f"(c[2]), "+f"(c[3])
                 : "r"(a[0]), "r"(a[1]), "r"(a[2]), "r"(a[3]), "r"(b[0]), "r"(b[1]));
}

// ---------------- 1) ternary scales ----------------
__global__ void scales_kernel(const float* __restrict__ Wq, const float* __restrict__ Wk,
                              const float* __restrict__ Wv, const float* __restrict__ Wo)
{
    const float* W = blockIdx.x==0?Wq: blockIdx.x==1?Wk: blockIdx.x==2?Wv:Wo;
    __shared__ float red[256];
    float a = 0.f;
    for (int i = threadIdx.x; i < DM*DM; i += 256) a += fabsf(W[i]);
    red[threadIdx.x] = a; __syncthreads();
    for (int o = 128; o > 0; o >>= 1) {
        if (threadIdx.x < o) red[threadIdx.x] += red[threadIdx.x + o];
        __syncthreads();
    }
    if (threadIdx.x == 0) {
        float alpha = red[0] * (1.0f/(DM*DM)) + 1e-12f;
        float e = rintf(log2f(alpha));
        e = fminf(fmaxf(e, -4.f), 4.f);
        g_s [blockIdx.x] = exp2f(e);
        g_si[blockIdx.x] = exp2f(-e);
    }
}

// ---------------- 2a) weights -> ternary bf16 (exact) ----------------
__global__ void convW_kernel(const float* __restrict__ Wq, const float* __restrict__ Wk,
                             const float* __restrict__ Wv, const float* __restrict__ Wo)
{
    int i = blockIdx.x * 256 + threadIdx.x;
    int mat = i >> 18;
    const float* W = mat==0?Wq: mat==1?Wk: mat==2?Wv:Wo;
    float v = W[i & 262143];
    float t = fminf(fmaxf(rintf(v * g_si[mat]), -1.f), 1.f) * g_s[mat];
    g_wt[i] = __float2bfloat16_rn(t);
}

// ---------------- 2b) 3-way exact bf16 split ----------------
__global__ void convX_kernel(const float* __restrict__ xin, int which)
{
    int i = blockIdx.x * 256 + threadIdx.x;
    const float* src = which ? g_attn : xin;
    __nv_bfloat16* dst = which ? g_as : g_xs;
    float v = src[i];
    __nv_bfloat16 h1 = __float2bfloat16_rn(v);
    float r1 = v - __bfloat162float(h1);
    __nv_bfloat16 h2 = __float2bfloat16_rn(r1);
    float r2 = r1 - __bfloat162float(h2);
    __nv_bfloat16 h3 = __float2bfloat16_rn(r2);
    dst[i] = h1; dst[i + 1048576] = h2; dst[i + 2097152] = h3;
}

// ---------------- 3) HMMA GEMM: D[128x128] = sum_splits A_s @ ternW^T ----------------
// smem: As 16KB | Bs 16KB | tbl 2KB  (static, 34.8KB)
__global__ __launch_bounds__(256) void mma_gemm_kernel(
    const float* __restrict__ bias, const float* __restrict__ phi_table,
    float* __restrict__ Out, int mode)
{
    __shared__ __align__(1024) char smA[16384];
    __shared__ __align__(1024) char smB[16384];
    __shared__ float tbl[512];

    const int tid = threadIdx.x;
    const int wid = tid >> 5, lane = tid & 31;
    const int wm = wid >> 2, wn = wid & 3;       // 2 x 4 warp grid

    if (mode == 0) { tbl[tid] = phi_table[tid]; tbl[tid+256] = phi_table[tid+256]; }

    const int m0  = blockIdx.y * 128;
    const int n0g = blockIdx.x * 128;
    const int mat = (mode == 0) ? (n0g >> 9) : 3;
    const int nb0 = (mode == 0) ? (n0g & 511) : n0g;

    const __nv_bfloat16* Aall = (mode == 0) ? g_xs : g_as;
    const __nv_bfloat16* Wbase = g_wt + (size_t)(mat * 512 + nb0) * 512;

    const uint32_t sA = smem_u32(smA);
    const uint32_t sB = smem_u32(smB);

    // per-thread load coords: 4 chunks of 16B for A and B each
    int lrow[4], lcol[4];
    #pragma unroll
    for (int i = 0; i < 4; i++) { int c = i*256 + tid; lrow[i] = c >> 3; lcol[i] = c & 7; }

    float acc[4][4][4];
    #pragma unroll
    for (int i = 0; i < 4; i++)
        #pragma unroll
        for (int j = 0; j < 4; j++)
            #pragma unroll
            for (int k = 0; k < 4; k++) acc[i][j][k] = 0.f;

    // ldmatrix addresses (fixed per thread, per ks they shift by 32B)
    const int t16 = lane & 15;
    uint32_t a_off[4];                            // 4 mtiles
    #pragma unroll
    for (int i = 0; i < 4; i++) {
        uint32_t o = (uint32_t)(wm*64 + i*16 + (t16 & 15)) * 128 + (lane >> 4) * 16;
        a_off[i] = o;                             // + ks*32, then SWZ
    }
    uint32_t b_off[4];                            // 4 ntiles
    #pragma unroll
    for (int j = 0; j < 4; j++) {
        uint32_t o = (uint32_t)(wn*32 + j*8 + (t16 & 7)) * 128 + ((t16 >> 3) & 1) * 16;
        b_off[j] = o;
    }

    uint4 ra[4], rb[4];
    // preload panel 0
    {
        const __nv_bfloat16* Ab = Aall;           // split 0, kp 0
        #pragma unroll
        for (int i = 0; i < 4; i++) {
            ra[i] = *(const uint4*)(Ab + (size_t)(m0 + lrow[i]) * 512 + lcol[i] * 8);
            rb[i] = *(const uint4*)(Wbase + (size_t)lrow[i] * 512 + lcol[i] * 8);
        }
    }

    #pragma unroll 1
    for (int p = 0; p < 24; p++) {
        // store current panel
        #pragma unroll
        for (int i = 0; i < 4; i++) {
            uint32_t off = (uint32_t)lrow[i] * 128 + lcol[i] * 16;
            uint32_t sw = SWZ(off);
            *(uint4*)(smA + sw) = ra[i];
            *(uint4*)(smB + sw) = rb[i];
        }
        __syncthreads();

        // prefetch next panel into regs
        if (p < 23) {
            int pn = p + 1;
            int split = pn >> 3, kp = (pn & 7) * 64;
            const __nv_bfloat16* Ab = Aall + (size_t)split * 1048576 + kp;
            const __nv_bfloat16* Bb = Wbase + kp;
            #pragma unroll
            for (int i = 0; i < 4; i++) {
                ra[i] = *(const uint4*)(Ab + (size_t)(m0 + lrow[i]) * 512 + lcol[i] * 8);
                rb[i] = *(const uint4*)(Bb + (size_t)lrow[i] * 512 + lcol[i] * 8);
            }
        }

        // compute panel from SMEM: 4 k-steps of 16
        #pragma unroll
        for (int ks = 0; ks < 4; ks++) {
            uint32_t bf[4][2];
            #pragma unroll
            for (int j = 0; j < 4; j++)
                ldmx2(bf[j], sB + SWZ(b_off[j] + ks*32));
            #pragma unroll
            for (int i = 0; i < 4; i++) {
                uint32_t af[4];
                ldmx4(af, sA + SWZ(a_off[i] + ks*32));
                #pragma unroll
                for (int j = 0; j < 4; j++)
                    mma16816(acc[i][j], af, bf[j]);
            }
        }
        __syncthreads();
    }

    // ---------------- epilogue ----------------
    const int lr4 = lane >> 2, lc2 = (lane & 3) * 2;
    if (mode == 0) {
        float* dst = (mat == 0) ? g_phiQ : (mat == 1) ? g_phiK : g_V;
        #pragma unroll
        for (int i = 0; i < 4; i++) {
            #pragma unroll
            for (int half = 0; half < 2; half++) {
                int m = m0 + wm*64 + i*16 + lr4 + half*8;
                int b = m >> 10, t = m & 1023;
                #pragma unroll
                for (int j = 0; j < 4; j++) {
                    int nc = nb0 + wn*32 + j*8 + lc2;
                    float v0 = acc[i][j][half*2+0];
                    float v1 = acc[i][j][half*2+1];
                    if (mat < 2) {
                        int i00 = min(max((int)rintf(__fdiv_rn(v0, 0.1f)) + 128, 0), 255);
                        int i01 = min(max((int)rintf(__fdiv_rn(v0, 0.2f)) + 128, 0), 255);
                        int i10 = min(max((int)rintf(__fdiv_rn(v1, 0.1f)) + 128, 0), 255);
                        int i11 = min(max((int)rintf(__fdiv_rn(v1, 0.2f)) + 128, 0), 255);
                        v0 = tbl[i00] + tbl[256 + i01];
                        v1 = tbl[i10] + tbl[256 + i11];
                    }
                    size_t base = ((size_t)((b << 3) + (nc >> 6)) * 1024 + t) * 64 + (nc & 63);
                    dst[base] = v0;
                    dst[base + 1] = v1;
                }
            }
        }
    } else {
        #pragma unroll
        for (int i = 0; i < 4; i++) {
            #pragma unroll
            for (int half = 0; half < 2; half++) {
                int m = m0 + wm*64 + i*16 + lr4 + half*8;
                #pragma unroll
                for (int j = 0; j < 4; j++) {
                    int n = n0g + wn*32 + j*8 + lc2;
                    Out[(size_t)m * 512 + n]     = acc[i][j][half*2+0] + bias[n];
                    Out[(size_t)m * 512 + n + 1] = acc[i][j][half*2+1] + bias[n+1];
                }
            }
        }
    }
}

// ---------------- 4) per-chunk K^T V and K colsum ----------------
__global__ __launch_bounds__(256) void chunksum_kernel()
{
    const int chunk = blockIdx.x, bh = blockIdx.y;
    __shared__ float Kt[CH*64];
    __shared__ float Vt[CH*64];
    const int tid = threadIdx.x;
    const float* Kg = g_phiK + (bh*TT + chunk*CH) * 64;
    const float* Vg = g_V    + (bh*TT + chunk*CH) * 64;
    for (int i = tid; i < CH*16; i += 256) {
        ((float4*)Kt)[i] = ((const float4*)Kg)[i];
        ((float4*)Vt)[i] = ((const float4*)Vg)[i];
    }
    __syncthreads();
    const int d0 = (tid >> 4) * 4, e0 = (tid & 15) * 4;
    float acc[4][4] = {};
    for (int t = 0; t < CH; t++) {
        float a0=Kt[t*64+d0+0], a1=Kt[t*64+d0+1], a2=Kt[t*64+d0+2], a3=Kt[t*64+d0+3];
        float b0=Vt[t*64+e0+0], b1=Vt[t*64+e0+1], b2=Vt[t*64+e0+2], b3=Vt[t*64+e0+3];
        acc[0][0]+=a0*b0; acc[0][1]+=a0*b1; acc[0][2]+=a0*b2; acc[0][3]+=a0*b3;
        acc[1][0]+=a1*b0; acc[1][1]+=a1*b1; acc[1][2]+=a1*b2; acc[1][3]+=a1*b3;
        acc[2][0]+=a2*b0; acc[2][1]+=a2*b1; acc[2][2]+=a2*b2; acc[2][3]+=a2*b3;
        acc[3][0]+=a3*b0; acc[3][1]+=a3*b1; acc[3][2]+=a3*b2; acc[3][3]+=a3*b3;
    }
    float* kvo = g_kv + (bh*NCH + chunk) * 4096;
    #pragma unroll
    for (int r = 0; r < 4; r++)
        #pragma unroll
        for (int c = 0; c < 4; c++)
            kvo[(d0+r)*64 + e0+c] = acc[r][c];
    if (tid < 64) {
        float su = 0.f;
        for (int t = 0; t < CH; t++) su += Kt[t*64 + tid];
        g_ks[(bh*NCH + chunk)*64 + tid] = su;
    }
}

// ---------------- 5) exclusive prefix over chunks ----------------
__global__ void prefix_kernel()
{
    const int bh = blockIdx.y;
    const int e = blockIdx.x * 256 + threadIdx.x;
    if (e < 4096) {
        float run = 0.f;
        float* base = g_kv + bh*NCH*4096 + e;
        #pragma unroll
        for (int c = 0; c < NCH; c++) { float v = base[c*4096]; base[c*4096] = run; run += v; }
    } else if (e < 4096 + 64) {
        const int d = e - 4096;
        float run = 0.f;
        float* base = g_ks + bh*NCH*64 + d;
        #pragma unroll
        for (int c = 0; c < NCH; c++) { float v = base[c*64]; base[c*64] = run; run += v; }
    }
}

// ---------------- 6) chunked causal attention output ----------------
extern __shared__ float dsm[];
__global__ __launch_bounds__(256) void attn_kernel()
{
    const int chunk = blockIdx.x, bh = blockIdx.y;
    float* Qb = dsm;
    float* Kb = dsm + 64*64;
    float* Sb = dsm + 64*64 + 64*65;
    const int tid = threadIdx.x;

    const float* Qg = g_phiQ + (bh*TT + chunk*CH) * 64;
    const float* Kg = g_phiK + (bh*TT + chunk*CH) * 64;
    for (int i = tid; i < 1024; i += 256) ((float4*)Qb)[i] = ((const float4*)Qg)[i];
    for (int i = tid; i < 1024; i += 256) {
        int r = i >> 4, cc = (i & 15) << 2;
        float4 v = ((const float4*)Kg)[i];
        Kb[r*65+cc+0]=v.x; Kb[r*65+cc+1]=v.y; Kb[r*65+cc+2]=v.z; Kb[r*65+cc+3]=v.w;
    }
    __syncthreads();

    const int g1 = tid >> 4, g2 = tid & 15;
    const int i0 = g1 * 4;

    {
        const int j0 = g2 * 4;
        float sacc[4][4] = {};
        for (int d = 0; d < 64; d++) {
            float a0=Qb[(i0+0)*64+d], a1=Qb[(i0+1)*64+d], a2=Qb[(i0+2)*64+d], a3=Qb[(i0+3)*64+d];
            float b0=Kb[(j0+0)*65+d], b1=Kb[(j0+1)*65+d], b2=Kb[(j0+2)*65+d], b3=Kb[(j0+3)*65+d];
            sacc[0][0]+=a0*b0; sacc[0][1]+=a0*b1; sacc[0][2]+=a0*b2; sacc[0][3]+=a0*b3;
            sacc[1][0]+=a1*b0; sacc[1][1]+=a1*b1; sacc[1][2]+=a1*b2; sacc[1][3]+=a1*b3;
            sacc[2][0]+=a2*b0; sacc[2][1]+=a2*b1; sacc[2][2]+=a2*b2; sacc[2][3]+=a2*b3;
            sacc[3][0]+=a3*b0; sacc[3][1]+=a3*b1; sacc[3][2]+=a3*b2; sacc[3][3]+=a3*b3;
        }
        #pragma unroll
        for (int r = 0; r < 4; r++)
            #pragma unroll
            for (int c = 0; c < 4; c++)
                Sb[(i0+r)*64 + j0+c] = sacc[r][c];
    }
    __syncthreads();

    {
        const float* Vg = g_V + (bh*TT + chunk*CH) * 64;
        for (int i = tid; i < 1024; i += 256) {
            int r = i >> 4, cc = (i & 15) << 2;
            float4 v = ((const float4*)Vg)[i];
            Kb[r*65+cc+0]=v.x; Kb[r*65+cc+1]=v.y; Kb[r*65+cc+2]=v.z; Kb[r*65+cc+3]=v.w;
        }
    }
    __syncthreads();

    const int e0 = g2 * 4;
    float acc[4][4] = {};
    for (int j = 0; j < 64; j++) {
        float b0=Kb[j*65+e0+0], b1=Kb[j*65+e0+1], b2=Kb[j*65+e0+2], b3=Kb[j*65+e0+3];
        #pragma unroll
        for (int r = 0; r < 4; r++) {
            float sv = (j <= i0 + r) ? Sb[(i0+r)*64 + j] : 0.f;
            acc[r][0]+=sv*b0; acc[r][1]+=sv*b1; acc[r][2]+=sv*b2; acc[r][3]+=sv*b3;
        }
    }
    __syncthreads();

    const float* stg = g_kv + (bh*NCH + chunk) * 4096;
    const float* ksg = g_ks + (bh*NCH + chunk) * 64;
    float zreg = 0.f;
    if (tid < 64) {
        const int i = tid;
        for (int j = 0; j <= i; j++) zreg += Sb[i*64 + j];
        for (int d = 0; d < 64; d++) zreg += Qb[i*64 + d] * ksg[d];
    }
    for (int i = tid; i < 1024; i += 256) {
        int r = i >> 4, cc = (i & 15) << 2;
        float4 v = ((const float4*)stg)[i];
        Kb[r*65+cc+0]=v.x; Kb[r*65+cc+1]=v.y; Kb[r*65+cc+2]=v.z; Kb[r*65+cc+3]=v.w;
    }
    if (tid < 64) Sb[tid] = zreg;
    __syncthreads();

    for (int d = 0; d < 64; d++) {
        float b0=Kb[d*65+e0+0], b1=Kb[d*65+e0+1], b2=Kb[d*65+e0+2], b3=Kb[d*65+e0+3];
        float a0=Qb[(i0+0)*64+d], a1=Qb[(i0+1)*64+d], a2=Qb[(i0+2)*64+d], a3=Qb[(i0+3)*64+d];
        acc[0][0]+=a0*b0; acc[0][1]+=a0*b1; acc[0][2]+=a0*b2; acc[0][3]+=a0*b3;
        acc[1][0]+=a1*b0; acc[1][1]+=a1*b1; acc[1][2]+=a1*b2; acc[1][3]+=a1*b3;
        acc[2][0]+=a2*b0; acc[2][1]+=a2*b1; acc[2][2]+=a2*b2; acc[2][3]+=a2*b3;
        acc[3][0]+=a3*b0; acc[3][1]+=a3*b1; acc[3][2]+=a3*b2; acc[3][3]+=a3*b3;
    }

    const int b = bh >> 3, h = bh & 7;
    #pragma unroll
    for (int r = 0; r < 4; r++) {
        const int t = chunk*CH + i0 + r;
        const float z = fmaxf(Sb[i0 + r], 1e-6f);
        float4 o;
        o.x = __fdiv_rn(acc[r][0], z);
        o.y = __fdiv_rn(acc[r][1], z);
        o.z = __fdiv_rn(acc[r][2], z);
        o.w = __fdiv_rn(acc[r][3], z);
        *(float4*)(g_attn + (b*TT + t)*DM + h*64 + e0) = o;
    }
}

// ---------------- launch ----------------
extern "C" void kernel_launch(void* const* d_in, const int* in_sizes, int n_in,
                              void* d_out, int out_size)
{
    const float* x   = (const float*)d_in[0];
    const float* Wq  = (const float*)d_in[1];
    const float* Wk  = (const float*)d_in[2];
    const float* Wv  = (const float*)d_in[3];
    const float* Wo  = (const float*)d_in[4];
    const float* bo  = (const float*)d_in[5];
    const float* phi = (const float*)d_in[6];
    float* out = (float*)d_out;

    const int attn_smem = (64*64 + 64*65 + 64*64) * sizeof(float); // 49408
    cudaFuncSetAttribute(attn_kernel, cudaFuncAttributeMaxDynamicSharedMemorySize, attn_smem);

    scales_kernel<<<4, 256>>>(Wq, Wk, Wv, Wo);
    convW_kernel<<<4096, 256>>>(Wq, Wk, Wv, Wo);
    convX_kernel<<<4096, 256>>>(x, 0);
    mma_gemm_kernel<<<dim3(12, 16), 256>>>(nullptr, phi, nullptr, 0);
    chunksum_kernel<<<dim3(NCH, BH), 256>>>();
    prefix_kernel<<<dim3(17, BH), 256>>>();
    attn_kernel<<<dim3(NCH, BH), 256, attn_smem>>>();
    convX_kernel<<<4096, 256>>>(x, 1);
    mma_gemm_kernel<<<dim3(4, 16), 256>>>(bo, nullptr, out, 1);
}

// round 5
// speedup vs baseline: 1.8398x; 1.1504x over previous
#include <cuda_runtime.h>
#include <cuda_bf16.h>
#include <math.h>
#include <stdint.h>

#define DM 512
#define TT 1024
#define BB 2
#define NH 8
#define BH 16      // BB*NH
#define CH 64      // chunk length
#define NCH 16     // TT/CH

// ---------------- scratch (device globals; no allocations) ----------------
__device__ float g_s[4];
__device__ float g_si[4];
__device__ float g_phiQ[BH*TT*64];          // (b,h,t,d)
__device__ float g_phiK[BH*TT*64];
__device__ float g_V  [BH*TT*64];
__device__ float g_kv [BH*NCH*64*64];
__device__ float g_ks [BH*NCH*64];
__device__ __nv_bfloat16 g_wt[4*512*512];   // ternary weights in bf16 (exact), [mat][n][k]
__device__ __nv_bfloat16 g_xs[3*2048*512];  // 3-way bf16 split of x
__device__ __nv_bfloat16 g_as[3*2048*512];  // 3-way bf16 split of attention output

// byte-offset swizzle within a 1KB atom (Swizzle<3,4,3>)
#define SWZ(o) ((o) ^ ((((o) >> 7) & 7) << 4))

__device__ __forceinline__ uint32_t smem_u32(const void* p) {
    uint32_t a;
    asm("{ .reg .u64 t; cvta.to.shared.u64 t, %1; cvt.u32.u64 %0, t; }" : "=r"(a) : "l"(p));
    return a;
}
__device__ __forceinline__ void ldmx4(uint32_t* r, uint32_t addr) {
    asm volatile("ldmatrix.sync.aligned.m8n8.x4.shared.b16 {%0,%1,%2,%3}, [%4];"
                 : "=r"(r[0]), "=r"(r[1]), "=r"(r[2]), "=r"(r[3]) : "r"(addr));
}
__device__ __forceinline__ void ldmx2(uint32_t* r, uint32_t addr) {
    asm volatile("ldmatrix.sync.aligned.m8n8.x2.shared.b16 {%0,%1}, [%2];"
                 : "=r"(r[0]), "=r"(r[1]) : "r"(addr));
}
__device__ __forceinline__ void mma16816(float* c, const uint32_t* a, const uint32_t* b) {
    asm volatile("mma.sync.aligned.m16n8k16.row.col.f32.bf16.bf16.f32 "
                 "{%0,%1,%2,%3},{%4,%5,%6,%7},{%8,%9},{%0,%1,%2,%3};"
                 : "+f"(c[0]), "+f"(c[1]), "+f"(c[2]), "+f"(c[3])
                 : "r"(a[0]), "r"(a[1]), "r"(a[2]), "r"(a[3]), "r"(b[0]), "r"(b[1]));
}
#define CP16(dst, src)  asm volatile("cp.async.cg.shared.global [%0], [%1], 16;" :: "r"(dst), "l"(src))
#define CP_COMMIT()     asm volatile("cp.async.commit_group;" ::: "memory")
#define CP_WAIT1()      asm volatile("cp.async.wait_group 1;" ::: "memory")

// ---------------- 1) ternary scales ----------------
__global__ void scales_kernel(const float* __restrict__ Wq, const float* __restrict__ Wk,
                              const float* __restrict__ Wv, const float* __restrict__ Wo)
{
    const float* W = blockIdx.x==0?Wq: blockIdx.x==1?Wk: blockIdx.x==2?Wv:Wo;
    __shared__ float red[256];
    float a = 0.f;
    for (int i = threadIdx.x; i < DM*DM; i += 256) a += fabsf(W[i]);
    red[threadIdx.x] = a; __syncthreads();
    for (int o = 128; o > 0; o >>= 1) {
        if (threadIdx.x < o) red[threadIdx.x] += red[threadIdx.x + o];
        __syncthreads();
    }
    if (threadIdx.x == 0) {
        float alpha = red[0] * (1.0f/(DM*DM)) + 1e-12f;
        float e = rintf(log2f(alpha));
        e = fminf(fmaxf(e, -4.f), 4.f);
        g_s [blockIdx.x] = exp2f(e);
        g_si[blockIdx.x] = exp2f(-e);
    }
}

// ---------------- 2) fused: weights->ternary bf16  +  3-way exact split of x ----------------
__global__ void conv_kernel(const float* __restrict__ xin,
                            const float* __restrict__ Wq, const float* __restrict__ Wk,
                            const float* __restrict__ Wv, const float* __restrict__ Wo)
{
    int bid = blockIdx.x;
    if (bid < 4096) {
        int i = bid * 256 + threadIdx.x;
        int mat = i >> 18;
        const float* W = mat==0?Wq: mat==1?Wk: mat==2?Wv:Wo;
        float v = W[i & 262143];
        float t = fminf(fmaxf(rintf(v * g_si[mat]), -1.f), 1.f) * g_s[mat];
        g_wt[i] = __float2bfloat16_rn(t);
    } else {
        int i = (bid - 4096) * 256 + threadIdx.x;
        float v = xin[i];
        __nv_bfloat16 h1 = __float2bfloat16_rn(v);
        float r1 = v - __bfloat162float(h1);
        __nv_bfloat16 h2 = __float2bfloat16_rn(r1);
        float r2 = r1 - __bfloat162float(h2);
        g_xs[i] = h1; g_xs[i + 1048576] = h2; g_xs[i + 2097152] = __float2bfloat16_rn(r2);
    }
}

// ---------------- 3) HMMA GEMM with cp.async 3-stage pipeline ----------------
// dyn smem: tbl 2KB @0 | stage s: A 16KB + B 16KB @ 2048 + s*32768   (total 100352 B)
extern __shared__ char DSM[];
__global__ __launch_bounds__(256, 2) void mma_gemm_kernel(
    const float* __restrict__ bias, const float* __restrict__ phi_table,
    float* __restrict__ Out, int mode)
{
    float* tbl = (float*)DSM;
    const uint32_t sbase = smem_u32(DSM);

    const int tid = threadIdx.x;
    const int wid = tid >> 5, lane = tid & 31;
    const int wm = wid >> 2, wn = wid & 3;       // 2 x 4 warp grid

    if (mode == 0) { tbl[tid] = phi_table[tid]; tbl[tid+256] = phi_table[tid+256]; }

    const int m0  = blockIdx.y * 128;
    const int n0g = blockIdx.x * 128;
    const int mat = (mode == 0) ? (n0g >> 9) : 3;
    const int nb0 = (mode == 0) ? (n0g & 511) : n0g;

    const __nv_bfloat16* Aall = (mode == 0) ? g_xs : g_as;
    const __nv_bfloat16* Wbase = g_wt + (size_t)(mat * 512 + nb0) * 512;

    // per-thread cp.async coords: 4 chunks of 16B for A and B each
    int lrow[4], lcol[4];
    #pragma unroll
    for (int i = 0; i < 4; i++) { int c = i*256 + tid; lrow[i] = c >> 3; lcol[i] = c & 7; }
    uint32_t swoff[4];
    #pragma unroll
    for (int i = 0; i < 4; i++) {
        uint32_t off = (uint32_t)lrow[i] * 128 + lcol[i] * 16;
        swoff[i] = SWZ(off);
    }

    float acc[4][4][4];
    #pragma unroll
    for (int i = 0; i < 4; i++)
        #pragma unroll
        for (int j = 0; j < 4; j++)
            #pragma unroll
            for (int k = 0; k < 4; k++) acc[i][j][k] = 0.f;

    // ldmatrix fragment offsets (within a stage), +ks*32 per k-step, then SWZ
    const int t16 = lane & 15;
    uint32_t a_off[4];
    #pragma unroll
    for (int i = 0; i < 4; i++)
        a_off[i] = (uint32_t)(wm*64 + i*16 + t16) * 128 + (lane >> 4) * 16;
    uint32_t b_off[4];
    #pragma unroll
    for (int j = 0; j < 4; j++)
        b_off[j] = (uint32_t)(wn*32 + j*8 + (t16 & 7)) * 128 + ((t16 >> 3) & 1) * 16;

    const int NP = 24;                            // 3 splits x 8 k-panels

    // panel issue: global -> smem stage (p % 3) via cp.async
    auto issue = [&](int p) {
        if (p < NP) {
            int split = p >> 3, kp = (p & 7) * 64;
            const __nv_bfloat16* Ab = Aall + (size_t)split * 1048576 + kp;
            const __nv_bfloat16* Bb = Wbase + kp;
            uint32_t bufA = sbase + 2048 + (uint32_t)(p % 3) * 32768;
            uint32_t bufB = bufA + 16384;
            #pragma unroll
            for (int i = 0; i < 4; i++) {
                CP16(bufA + swoff[i], Ab + (size_t)(m0 + lrow[i]) * 512 + lcol[i] * 8);
                CP16(bufB + swoff[i], Bb + (size_t)lrow[i] * 512 + lcol[i] * 8);
            }
        }
        CP_COMMIT();
    };

    issue(0); issue(1);

    #pragma unroll 1
    for (int p = 0; p < NP; p++) {
        CP_WAIT1();
        __syncthreads();
        issue(p + 2);                             // overwrites stage (p-1)%3 — all readers past barrier

        const uint32_t sA = sbase + 2048 + (uint32_t)(p % 3) * 32768;
        const uint32_t sB = sA + 16384;
        #pragma unroll
        for (int ks = 0; ks < 4; ks++) {
            uint32_t bf[4][2];
            #pragma unroll
            for (int j = 0; j < 4; j++)
                ldmx2(bf[j], sB + SWZ(b_off[j] + ks*32));
            #pragma unroll
            for (int i = 0; i < 4; i++) {
                uint32_t af[4];
                ldmx4(af, sA + SWZ(a_off[i] + ks*32));
                #pragma unroll
                for (int j = 0; j < 4; j++)
                    mma16816(acc[i][j], af, bf[j]);
            }
        }
    }
    __syncthreads();

    // ---------------- epilogue ----------------
    const int lr4 = lane >> 2, lc2 = (lane & 3) * 2;
    if (mode == 0) {
        float* dst = (mat == 0) ? g_phiQ : (mat == 1) ? g_phiK : g_V;
        #pragma unroll
        for (int i = 0; i < 4; i++) {
            #pragma unroll
            for (int half = 0; half < 2; half++) {
                int m = m0 + wm*64 + i*16 + lr4 + half*8;
                int b = m >> 10, t = m & 1023;
                #pragma unroll
                for (int j = 0; j < 4; j++) {
                    int nc = nb0 + wn*32 + j*8 + lc2;
                    float v0 = acc[i][j][half*2+0];
                    float v1 = acc[i][j][half*2+1];
                    if (mat < 2) {
                        int i00 = min(max((int)rintf(__fdiv_rn(v0, 0.1f)) + 128, 0), 255);
                        int i01 = min(max((int)rintf(__fdiv_rn(v0, 0.2f)) + 128, 0), 255);
                        int i10 = min(max((int)rintf(__fdiv_rn(v1, 0.1f)) + 128, 0), 255);
                        int i11 = min(max((int)rintf(__fdiv_rn(v1, 0.2f)) + 128, 0), 255);
                        v0 = tbl[i00] + tbl[256 + i01];
                        v1 = tbl[i10] + tbl[256 + i11];
                    }
                    size_t base = ((size_t)((b << 3) + (nc >> 6)) * 1024 + t) * 64 + (nc & 63);
                    dst[base] = v0;
                    dst[base + 1] = v1;
                }
            }
        }
    } else {
        #pragma unroll
        for (int i = 0; i < 4; i++) {
            #pragma unroll
            for (int half = 0; half < 2; half++) {
                int m = m0 + wm*64 + i*16 + lr4 + half*8;
                #pragma unroll
                for (int j = 0; j < 4; j++) {
                    int n = n0g + wn*32 + j*8 + lc2;
                    Out[(size_t)m * 512 + n]     = acc[i][j][half*2+0] + bias[n];
                    Out[(size_t)m * 512 + n + 1] = acc[i][j][half*2+1] + bias[n+1];
                }
            }
        }
    }
}

// ---------------- 4) per-chunk K^T V and K colsum ----------------
__global__ __launch_bounds__(256) void chunksum_kernel()
{
    const int chunk = blockIdx.x, bh = blockIdx.y;
    __shared__ float Kt[CH*64];
    __shared__ float Vt[CH*64];
    const int tid = threadIdx.x;
    const float* Kg = g_phiK + (bh*TT + chunk*CH) * 64;
    const float* Vg = g_V    + (bh*TT + chunk*CH) * 64;
    for (int i = tid; i < CH*16; i += 256) {
        ((float4*)Kt)[i] = ((const float4*)Kg)[i];
        ((float4*)Vt)[i] = ((const float4*)Vg)[i];
    }
    __syncthreads();
    const int d0 = (tid >> 4) * 4, e0 = (tid & 15) * 4;
    float acc[4][4] = {};
    for (int t = 0; t < CH; t++) {
        float a0=Kt[t*64+d0+0], a1=Kt[t*64+d0+1], a2=Kt[t*64+d0+2], a3=Kt[t*64+d0+3];
        float b0=Vt[t*64+e0+0], b1=Vt[t*64+e0+1], b2=Vt[t*64+e0+2], b3=Vt[t*64+e0+3];
        acc[0][0]+=a0*b0; acc[0][1]+=a0*b1; acc[0][2]+=a0*b2; acc[0][3]+=a0*b3;
        acc[1][0]+=a1*b0; acc[1][1]+=a1*b1; acc[1][2]+=a1*b2; acc[1][3]+=a1*b3;
        acc[2][0]+=a2*b0; acc[2][1]+=a2*b1; acc[2][2]+=a2*b2; acc[2][3]+=a2*b3;
        acc[3][0]+=a3*b0; acc[3][1]+=a3*b1; acc[3][2]+=a3*b2; acc[3][3]+=a3*b3;
    }
    float* kvo = g_kv + (bh*NCH + chunk) * 4096;
    #pragma unroll
    for (int r = 0; r < 4; r++)
        #pragma unroll
        for (int c = 0; c < 4; c++)
            kvo[(d0+r)*64 + e0+c] = acc[r][c];
    if (tid < 64) {
        float su = 0.f;
        for (int t = 0; t < CH; t++) su += Kt[t*64 + tid];
        g_ks[(bh*NCH + chunk)*64 + tid] = su;
    }
}

// ---------------- 5) exclusive prefix over chunks ----------------
__global__ void prefix_kernel()
{
    const int bh = blockIdx.y;
    const int e = blockIdx.x * 256 + threadIdx.x;
    if (e < 4096) {
        float run = 0.f;
        float* base = g_kv + bh*NCH*4096 + e;
        #pragma unroll
        for (int c = 0; c < NCH; c++) { float v = base[c*4096]; base[c*4096] = run; run += v; }
    } else if (e < 4096 + 64) {
        const int d = e - 4096;
        float run = 0.f;
        float* base = g_ks + bh*NCH*64 + d;
        #pragma unroll
        for (int c = 0; c < NCH; c++) { float v = base[c*64]; base[c*64] = run; run += v; }
    }
}

// ---------------- 6) chunked causal attention + fused bf16-split epilogue ----------------
__global__ __launch_bounds__(256) void attn_kernel()
{
    float* dsm = (float*)DSM;
    const int chunk = blockIdx.x, bh = blockIdx.y;
    float* Qb = dsm;
    float* Kb = dsm + 64*64;
    float* Sb = dsm + 64*64 + 64*65;
    const int tid = threadIdx.x;

    const float* Qg = g_phiQ + (bh*TT + chunk*CH) * 64;
    const float* Kg = g_phiK + (bh*TT + chunk*CH) * 64;
    for (int i = tid; i < 1024; i += 256) ((float4*)Qb)[i] = ((const float4*)Qg)[i];
    for (int i = tid; i < 1024; i += 256) {
        int r = i >> 4, cc = (i & 15) << 2;
        float4 v = ((const float4*)Kg)[i];
        Kb[r*65+cc+0]=v.x; Kb[r*65+cc+1]=v.y; Kb[r*65+cc+2]=v.z; Kb[r*65+cc+3]=v.w;
    }
    __syncthreads();

    const int g1 = tid >> 4, g2 = tid & 15;
    const int i0 = g1 * 4;

    {
        const int j0 = g2 * 4;
        float sacc[4][4] = {};
        for (int d = 0; d < 64; d++) {
            float a0=Qb[(i0+0)*64+d], a1=Qb[(i0+1)*64+d], a2=Qb[(i0+2)*64+d], a3=Qb[(i0+3)*64+d];
            float b0=Kb[(j0+0)*65+d], b1=Kb[(j0+1)*65+d], b2=Kb[(j0+2)*65+d], b3=Kb[(j0+3)*65+d];
            sacc[0][0]+=a0*b0; sacc[0][1]+=a0*b1; sacc[0][2]+=a0*b2; sacc[0][3]+=a0*b3;
            sacc[1][0]+=a1*b0; sacc[1][1]+=a1*b1; sacc[1][2]+=a1*b2; sacc[1][3]+=a1*b3;
            sacc[2][0]+=a2*b0; sacc[2][1]+=a2*b1; sacc[2][2]+=a2*b2; sacc[2][3]+=a2*b3;
            sacc[3][0]+=a3*b0; sacc[3][1]+=a3*b1; sacc[3][2]+=a3*b2; sacc[3][3]+=a3*b3;
        }
        #pragma unroll
        for (int r = 0; r < 4; r++)
            #pragma unroll
            for (int c = 0; c < 4; c++)
                Sb[(i0+r)*64 + j0+c] = sacc[r][c];
    }
    __syncthreads();

    {
        const float* Vg = g_V + (bh*TT + chunk*CH) * 64;
        for (int i = tid; i < 1024; i += 256) {
            int r = i >> 4, cc = (i & 15) << 2;
            float4 v = ((const float4*)Vg)[i];
            Kb[r*65+cc+0]=v.x; Kb[r*65+cc+1]=v.y; Kb[r*65+cc+2]=v.z; Kb[r*65+cc+3]=v.w;
        }
    }
    __syncthreads();

    const int e0 = g2 * 4;
    float acc[4][4] = {};
    for (int j = 0; j < 64; j++) {
        float b0=Kb[j*65+e0+0], b1=Kb[j*65+e0+1], b2=Kb[j*65+e0+2], b3=Kb[j*65+e0+3];
        #pragma unroll
        for (int r = 0; r < 4; r++) {
            float sv = (j <= i0 + r) ? Sb[(i0+r)*64 + j] : 0.f;
            acc[r][0]+=sv*b0; acc[r][1]+=sv*b1; acc[r][2]+=sv*b2; acc[r][3]+=sv*b3;
        }
    }
    __syncthreads();

    const float* stg = g_kv + (bh*NCH + chunk) * 4096;
    const float* ksg = g_ks + (bh*NCH + chunk) * 64;
    float zreg = 0.f;
    if (tid < 64) {
        const int i = tid;
        for (int j = 0; j <= i; j++) zreg += Sb[i*64 + j];
        for (int d = 0; d < 64; d++) zreg += Qb[i*64 + d] * ksg[d];
    }
    for (int i = tid; i < 1024; i += 256) {
        int r = i >> 4, cc = (i & 15) << 2;
        float4 v = ((const float4*)stg)[i];
        Kb[r*65+cc+0]=v.x; Kb[r*65+cc+1]=v.y; Kb[r*65+cc+2]=v.z; Kb[r*65+cc+3]=v.w;
    }
    if (tid < 64) Sb[tid] = zreg;
    __syncthreads();

    for (int d = 0; d < 64; d++) {
        float b0=Kb[d*65+e0+0], b1=Kb[d*65+e0+1], b2=Kb[d*65+e0+2], b3=Kb[d*65+e0+3];
        float a0=Qb[(i0+0)*64+d], a1=Qb[(i0+1)*64+d], a2=Qb[(i0+2)*64+d], a3=Qb[(i0+3)*64+d];
        acc[0][0]+=a0*b0; acc[0][1]+=a0*b1; acc[0][2]+=a0*b2; acc[0][3]+=a0*b3;
        acc[1][0]+=a1*b0; acc[1][1]+=a1*b1; acc[1][2]+=a1*b2; acc[1][3]+=a1*b3;
        acc[2][0]+=a2*b0; acc[2][1]+=a2*b1; acc[2][2]+=a2*b2; acc[2][3]+=a2*b3;
        acc[3][0]+=a3*b0; acc[3][1]+=a3*b1; acc[3][2]+=a3*b2; acc[3][3]+=a3*b3;
    }

    // normalized output -> exact 3-way bf16 split, written directly (no g_attn pass)
    const int b = bh >> 3, h = bh & 7;
    #pragma unroll
    for (int r = 0; r < 4; r++) {
        const int t = chunk*CH + i0 + r;
        const float z = fmaxf(Sb[i0 + r], 1e-6f);
        #pragma unroll
        for (int c = 0; c < 4; c++) {
            float o = __fdiv_rn(acc[r][c], z);
            size_t idx = ((size_t)(b*TT + t)) * DM + h*64 + e0 + c;
            __nv_bfloat16 h1 = __float2bfloat16_rn(o);
            float r1 = o - __bfloat162float(h1);
            __nv_bfloat16 h2 = __float2bfloat16_rn(r1);
            float r2 = r1 - __bfloat162float(h2);
            g_as[idx]           = h1;
            g_as[idx + 1048576] = h2;
            g_as[idx + 2097152] = __float2bfloat16_rn(r2);
        }
    }
}

// ---------------- launch ----------------
extern "C" void kernel_launch(void* const* d_in, const int* in_sizes, int n_in,
                              void* d_out, int out_size)
{
    const float* x   = (const float*)d_in[0];
    const float* Wq  = (const float*)d_in[1];
    const float* Wk  = (const float*)d_in[2];
    const float* Wv  = (const float*)d_in[3];
    const float* Wo  = (const float*)d_in[4];
    const float* bo  = (const float*)d_in[5];
    const float* phi = (const float*)d_in[6];
    float* out = (float*)d_out;

    const int attn_smem = (64*64 + 64*65 + 64*64) * sizeof(float); // 49408
    const int mma_smem  = 2048 + 3 * 32768;                        // 100352
    cudaFuncSetAttribute(attn_kernel, cudaFuncAttributeMaxDynamicSharedMemorySize, attn_smem);
    cudaFuncSetAttribute(mma_gemm_kernel, cudaFuncAttributeMaxDynamicSharedMemorySize, mma_smem);

    scales_kernel<<<4, 256>>>(Wq, Wk, Wv, Wo);
    conv_kernel<<<8192, 256>>>(x, Wq, Wk, Wv, Wo);
    mma_gemm_kernel<<<dim3(12, 16), 256, mma_smem>>>(nullptr, phi, nullptr, 0);
    chunksum_kernel<<<dim3(NCH, BH), 256>>>();
    prefix_kernel<<<dim3(17, BH), 256>>>();
    attn_kernel<<<dim3(NCH, BH), 256, attn_smem>>>();
    mma_gemm_kernel<<<dim3(4, 16), 256, mma_smem>>>(bo, nullptr, out, 1);
}

// round 6
// speedup vs baseline: 2.0746x; 1.1276x over previous
#include <cuda_runtime.h>
#include <cuda_bf16.h>
#include <math.h>
#include <stdint.h>

#define DM 512
#define TT 1024
#define BB 2
#define NH 8
#define BH 16      // BB*NH
#define CH 64      // chunk length
#define NCH 16     // TT/CH

// ---------------- scratch (device globals; no allocations) ----------------
__device__ float g_alpha[4];
__device__ float g_s[4];
__device__ float g_si[4];
__device__ float g_phiQ[BH*TT*64];          // (b,h,t,d)
__device__ float g_phiK[BH*TT*64];
__device__ float g_V  [BH*TT*64];
__device__ float g_kv [BH*NCH*64*64];
__device__ float g_ks [BH*NCH*64];
__device__ __nv_bfloat16 g_wt[4*512*512];   // ternary weights in bf16 (exact), [mat][n][k]
__device__ __nv_bfloat16 g_xs[3*2048*512];  // 3-way bf16 split of x
__device__ __nv_bfloat16 g_as[3*2048*512];  // 3-way bf16 split of attention output

// byte-offset swizzle within a 1KB atom (Swizzle<3,4,3>)
#define SWZ(o) ((o) ^ ((((o) >> 7) & 7) << 4))

__device__ __forceinline__ uint32_t smem_u32(const void* p) {
    uint32_t a;
    asm("{ .reg .u64 t; cvta.to.shared.u64 t, %1; cvt.u32.u64 %0, t; }" : "=r"(a) : "l"(p));
    return a;
}
__device__ __forceinline__ void ldmx4(uint32_t* r, uint32_t addr) {
    asm volatile("ldmatrix.sync.aligned.m8n8.x4.shared.b16 {%0,%1,%2,%3}, [%4];"
                 : "=r"(r[0]), "=r"(r[1]), "=r"(r[2]), "=r"(r[3]) : "r"(addr));
}
__device__ __forceinline__ void ldmx2(uint32_t* r, uint32_t addr) {
    asm volatile("ldmatrix.sync.aligned.m8n8.x2.shared.b16 {%0,%1}, [%2];"
                 : "=r"(r[0]), "=r"(r[1]) : "r"(addr));
}
__device__ __forceinline__ void mma16816(float* c, const uint32_t* a, const uint32_t* b) {
    asm volatile("mma.sync.aligned.m16n8k16.row.col.f32.bf16.bf16.f32 "
                 "{%0,%1,%2,%3},{%4,%5,%6,%7},{%8,%9},{%0,%1,%2,%3};"
                 : "+f"(c[0]), "+f"(c[1]), "+f"(c[2]), "+f"(c[3])
                 : "r"(a[0]), "r"(a[1]), "r"(a[2]), "r"(a[3]), "r"(b[0]), "r"(b[1]));
}
#define CP16(dst, src)  asm volatile("cp.async.cg.shared.global [%0], [%1], 16;" :: "r"(dst), "l"(src))
#define CP_COMMIT()     asm volatile("cp.async.commit_group;" ::: "memory")
#define CP_WAIT1()      asm volatile("cp.async.wait_group 1;" ::: "memory")

// ---------------- 1a) ternary scale partial |W| sums ----------------
__global__ void scales_part_kernel(const float* __restrict__ Wq, const float* __restrict__ Wk,
                                   const float* __restrict__ Wv, const float* __restrict__ Wo)
{
    const int mat = blockIdx.x >> 4;             // 16 blocks per matrix
    const float* W = mat==0?Wq: mat==1?Wk: mat==2?Wv:Wo;
    const float4* W4 = (const float4*)(W + (blockIdx.x & 15) * 16384);
    float a = 0.f;
    #pragma unroll 4
    for (int i = threadIdx.x; i < 4096; i += 256) {
        float4 v = W4[i];
        a += fabsf(v.x) + fabsf(v.y) + fabsf(v.z) + fabsf(v.w);
    }
    __shared__ float red[256];
    red[threadIdx.x] = a; __syncthreads();
    for (int o = 128; o > 0; o >>= 1) {
        if (threadIdx.x < o) red[threadIdx.x] += red[threadIdx.x + o];
        __syncthreads();
    }
    if (threadIdx.x == 0) atomicAdd(&g_alpha[mat], red[0]);
}

// ---------------- 1b) finalize scales ----------------
__global__ void scales_fin_kernel()
{
    int t = threadIdx.x;
    if (t < 4) {
        float alpha = g_alpha[t] * (1.0f/(DM*DM)) + 1e-12f;
        float e = rintf(log2f(alpha));
        e = fminf(fmaxf(e, -4.f), 4.f);
        g_s [t] = exp2f(e);
        g_si[t] = exp2f(-e);
    }
}

// ---------------- 2) fused: weights->ternary bf16  +  3-way exact split of x ----------------
__global__ void conv_kernel(const float* __restrict__ xin,
                            const float* __restrict__ Wq, const float* __restrict__ Wk,
                            const float* __restrict__ Wv, const float* __restrict__ Wo)
{
    int bid = blockIdx.x;
    if (bid < 4096) {
        int i = bid * 256 + threadIdx.x;
        int mat = i >> 18;
        const float* W = mat==0?Wq: mat==1?Wk: mat==2?Wv:Wo;
        float v = W[i & 262143];
        float t = fminf(fmaxf(rintf(v * g_si[mat]), -1.f), 1.f) * g_s[mat];
        g_wt[i] = __float2bfloat16_rn(t);
    } else {
        int i = (bid - 4096) * 256 + threadIdx.x;
        float v = xin[i];
        __nv_bfloat16 h1 = __float2bfloat16_rn(v);
        float r1 = v - __bfloat162float(h1);
        __nv_bfloat16 h2 = __float2bfloat16_rn(r1);
        float r2 = r1 - __bfloat162float(h2);
        g_xs[i] = h1; g_xs[i + 1048576] = h2; g_xs[i + 2097152] = __float2bfloat16_rn(r2);
    }
}

// ---------------- 3) HMMA GEMM with cp.async 3-stage pipeline ----------------
// dyn smem: tbl 2KB @0 | stage s: A 16KB + B 16KB @ 2048 + s*32768   (total 100352 B)
// mtiles: 4 -> 128-row tile (QKV), 2 -> 64-row tile (O-proj)
extern __shared__ char DSM[];
__global__ __launch_bounds__(256, 2) void mma_gemm_kernel(
    const float* __restrict__ bias, const float* __restrict__ phi_table,
    float* __restrict__ Out, int mode, int mtiles)
{
    float* tbl = (float*)DSM;
    const uint32_t sbase = smem_u32(DSM);

    const int tid = threadIdx.x;
    const int wid = tid >> 5, lane = tid & 31;
    const int wm = wid >> 2, wn = wid & 3;       // 2 x 4 warp grid

    if (mode == 0) { tbl[tid] = phi_table[tid]; tbl[tid+256] = phi_table[tid+256]; }

    const int m0  = blockIdx.y * (mtiles * 32);
    const int n0g = blockIdx.x * 128;
    const int mat = (mode == 0) ? (n0g >> 9) : 3;
    const int nb0 = (mode == 0) ? (n0g & 511) : n0g;

    const __nv_bfloat16* Aall = (mode == 0) ? g_xs : g_as;
    const __nv_bfloat16* Wbase = g_wt + (size_t)(mat * 512 + nb0) * 512;

    // per-thread cp.async coords: chunks of 16B (A: mtiles per thread, B: 4)
    int lrow[4], lcol[4];
    #pragma unroll
    for (int i = 0; i < 4; i++) { int c = i*256 + tid; lrow[i] = c >> 3; lcol[i] = c & 7; }
    uint32_t swoff[4];
    #pragma unroll
    for (int i = 0; i < 4; i++) {
        uint32_t off = (uint32_t)lrow[i] * 128 + lcol[i] * 16;
        swoff[i] = SWZ(off);
    }

    float acc[4][4][4];
    #pragma unroll
    for (int i = 0; i < 4; i++)
        #pragma unroll
        for (int j = 0; j < 4; j++)
            #pragma unroll
            for (int k = 0; k < 4; k++) acc[i][j][k] = 0.f;

    // ldmatrix fragment offsets (within a stage), +ks*32 per k-step, then SWZ
    const int t16 = lane & 15;
    uint32_t a_off[4];
    #pragma unroll
    for (int i = 0; i < 4; i++)
        a_off[i] = (uint32_t)(wm*(mtiles*16) + i*16 + t16) * 128 + (lane >> 4) * 16;
    uint32_t b_off[4];
    #pragma unroll
    for (int j = 0; j < 4; j++)
        b_off[j] = (uint32_t)(wn*32 + j*8 + (t16 & 7)) * 128 + ((t16 >> 3) & 1) * 16;

    const int NP = 24;                            // 3 splits x 8 k-panels

    // panel issue: global -> smem stage (p % 3) via cp.async
    auto issue = [&](int p) {
        if (p < NP) {
            int split = p >> 3, kp = (p & 7) * 64;
            const __nv_bfloat16* Ab = Aall + (size_t)split * 1048576 + kp;
            const __nv_bfloat16* Bb = Wbase + kp;
            uint32_t bufA = sbase + 2048 + (uint32_t)(p % 3) * 32768;
            uint32_t bufB = bufA + 16384;
            #pragma unroll
            for (int i = 0; i < 4; i++) {
                if (i < mtiles)
                    CP16(bufA + swoff[i], Ab + (size_t)(m0 + lrow[i]) * 512 + lcol[i] * 8);
                CP16(bufB + swoff[i], Bb + (size_t)lrow[i] * 512 + lcol[i] * 8);
            }
        }
        CP_COMMIT();
    };

    issue(0); issue(1);

    #pragma unroll 1
    for (int p = 0; p < NP; p++) {
        CP_WAIT1();
        __syncthreads();
        issue(p + 2);                             // overwrites stage (p-1)%3 — all readers past barrier

        const uint32_t sA = sbase + 2048 + (uint32_t)(p % 3) * 32768;
        const uint32_t sB = sA + 16384;
        #pragma unroll
        for (int ks = 0; ks < 4; ks++) {
            uint32_t bf[4][2];
            #pragma unroll
            for (int j = 0; j < 4; j++)
                ldmx2(bf[j], sB + SWZ(b_off[j] + ks*32));
            #pragma unroll
            for (int i = 0; i < 4; i++) {
                if (i < mtiles) {
                    uint32_t af[4];
                    ldmx4(af, sA + SWZ(a_off[i] + ks*32));
                    #pragma unroll
                    for (int j = 0; j < 4; j++)
                        mma16816(acc[i][j], af, bf[j]);
                }
            }
        }
    }
    __syncthreads();

    // ---------------- epilogue ----------------
    const int lr4 = lane >> 2, lc2 = (lane & 3) * 2;
    if (mode == 0) {
        float* dst = (mat == 0) ? g_phiQ : (mat == 1) ? g_phiK : g_V;
        #pragma unroll
        for (int i = 0; i < 4; i++) {
            #pragma unroll
            for (int half = 0; half < 2; half++) {
                int m = m0 + wm*64 + i*16 + lr4 + half*8;
                int b = m >> 10, t = m & 1023;
                #pragma unroll
                for (int j = 0; j < 4; j++) {
                    int nc = nb0 + wn*32 + j*8 + lc2;
                    float v0 = acc[i][j][half*2+0];
                    float v1 = acc[i][j][half*2+1];
                    if (mat < 2) {
                        int i00 = min(max((int)rintf(__fdiv_rn(v0, 0.1f)) + 128, 0), 255);
                        int i01 = min(max((int)rintf(__fdiv_rn(v0, 0.2f)) + 128, 0), 255);
                        int i10 = min(max((int)rintf(__fdiv_rn(v1, 0.1f)) + 128, 0), 255);
                        int i11 = min(max((int)rintf(__fdiv_rn(v1, 0.2f)) + 128, 0), 255);
                        v0 = tbl[i00] + tbl[256 + i01];
                        v1 = tbl[i10] + tbl[256 + i11];
                    }
                    size_t base = ((size_t)((b << 3) + (nc >> 6)) * 1024 + t) * 64 + (nc & 63);
                    dst[base] = v0;
                    dst[base + 1] = v1;
                }
            }
        }
    } else {
        #pragma unroll
        for (int i = 0; i < 4; i++) {
            if (i < mtiles) {
                #pragma unroll
                for (int half = 0; half < 2; half++) {
                    int m = m0 + wm*(mtiles*16) + i*16 + lr4 + half*8;
                    #pragma unroll
                    for (int j = 0; j < 4; j++) {
                        int n = n0g + wn*32 + j*8 + lc2;
                        Out[(size_t)m * 512 + n]     = acc[i][j][half*2+0] + bias[n];
                        Out[(size_t)m * 512 + n + 1] = acc[i][j][half*2+1] + bias[n+1];
                    }
                }
            }
        }
    }
}

// ---------------- 4) per-chunk K^T V and K colsum (float4 smem reads) ----------------
__global__ __launch_bounds__(256) void chunksum_kernel()
{
    const int chunk = blockIdx.x, bh = blockIdx.y;
    __shared__ float Kt[CH*64];
    __shared__ float Vt[CH*64];
    const int tid = threadIdx.x;
    const float* Kg = g_phiK + (bh*TT + chunk*CH) * 64;
    const float* Vg = g_V    + (bh*TT + chunk*CH) * 64;
    for (int i = tid; i < CH*16; i += 256) {
        ((float4*)Kt)[i] = ((const float4*)Kg)[i];
        ((float4*)Vt)[i] = ((const float4*)Vg)[i];
    }
    __syncthreads();
    const int d4 = tid >> 4, e4 = tid & 15;      // float4 indices
    const float4* Kt4 = (const float4*)Kt;
    const float4* Vt4 = (const float4*)Vt;
    float acc[4][4] = {};
    #pragma unroll 4
    for (int t = 0; t < CH; t++) {
        float4 a = Kt4[t*16 + d4];
        float4 b = Vt4[t*16 + e4];
        acc[0][0]+=a.x*b.x; acc[0][1]+=a.x*b.y; acc[0][2]+=a.x*b.z; acc[0][3]+=a.x*b.w;
        acc[1][0]+=a.y*b.x; acc[1][1]+=a.y*b.y; acc[1][2]+=a.y*b.z; acc[1][3]+=a.y*b.w;
        acc[2][0]+=a.z*b.x; acc[2][1]+=a.z*b.y; acc[2][2]+=a.z*b.z; acc[2][3]+=a.z*b.w;
        acc[3][0]+=a.w*b.x; acc[3][1]+=a.w*b.y; acc[3][2]+=a.w*b.z; acc[3][3]+=a.w*b.w;
    }
    float* kvo = g_kv + (bh*NCH + chunk) * 4096;
    #pragma unroll
    for (int r = 0; r < 4; r++) {
        float4 o = make_float4(acc[r][0], acc[r][1], acc[r][2], acc[r][3]);
        *(float4*)(kvo + (d4*4+r)*64 + e4*4) = o;
    }
    if (tid < 64) {
        float su = 0.f;
        for (int t = 0; t < CH; t++) su += Kt[t*64 + tid];
        g_ks[(bh*NCH + chunk)*64 + tid] = su;
    }
}

// ---------------- 5) exclusive prefix over chunks ----------------
__global__ void prefix_kernel()
{
    const int bh = blockIdx.y;
    const int e = blockIdx.x * 256 + threadIdx.x;
    if (e < 4096) {
        float run = 0.f;
        float* base = g_kv + bh*NCH*4096 + e;
        #pragma unroll
        for (int c = 0; c < NCH; c++) { float v = base[c*4096]; base[c*4096] = run; run += v; }
    } else if (e < 4096 + 64) {
        const int d = e - 4096;
        float run = 0.f;
        float* base = g_ks + bh*NCH*64 + d;
        #pragma unroll
        for (int c = 0; c < NCH; c++) { float v = base[c*64]; base[c*64] = run; run += v; }
    }
}

// ---------------- 6) chunked causal attention + fused bf16-split epilogue ----------------
// dyn smem: Qb[4096] | Kb[64*68=4352] | Sb[4096]  floats = 50176 B
__global__ __launch_bounds__(256) void attn_kernel()
{
    float* dsm = (float*)DSM;
    const int chunk = blockIdx.x, bh = blockIdx.y;
    float* Qb = dsm;
    float* Kb = dsm + 4096;
    float* Sb = dsm + 4096 + 4352;
    float4* Qb4 = (float4*)Qb;
    float4* Kb4 = (float4*)Kb;                   // stride 17 float4s (68 floats) for V/state
    const int tid = threadIdx.x;

    const float* Qg = g_phiQ + (bh*TT + chunk*CH) * 64;
    const float* Kg = g_phiK + (bh*TT + chunk*CH) * 64;
    for (int i = tid; i < 1024; i += 256) Qb4[i] = ((const float4*)Qg)[i];
    for (int i = tid; i < 1024; i += 256) {      // K row-major stride 65 (phase-1 layout)
        int r = i >> 4, cc = (i & 15) << 2;
        float4 v = ((const float4*)Kg)[i];
        Kb[r*65+cc+0]=v.x; Kb[r*65+cc+1]=v.y; Kb[r*65+cc+2]=v.z; Kb[r*65+cc+3]=v.w;
    }
    __syncthreads();

    const int g1 = tid >> 4, g2 = tid & 15;
    const int i0 = g1 * 4;

    // phase 1: S = phiQ @ phiK^T   (Qb via float4, Kb scalar stride-65; d ascending)
    {
        const int j0 = g2 * 4;
        float sacc[4][4] = {};
        for (int d4 = 0; d4 < 16; d4++) {
            float4 qa0 = Qb4[(i0+0)*16 + d4];
            float4 qa1 = Qb4[(i0+1)*16 + d4];
            float4 qa2 = Qb4[(i0+2)*16 + d4];
            float4 qa3 = Qb4[(i0+3)*16 + d4];
            const float* qp0 = (const float*)&qa0;
            const float* qp1 = (const float*)&qa1;
            const float* qp2 = (const float*)&qa2;
            const float* qp3 = (const float*)&qa3;
            #pragma unroll
            for (int dd = 0; dd < 4; dd++) {
                int d = d4*4 + dd;
                float b0=Kb[(j0+0)*65+d], b1=Kb[(j0+1)*65+d], b2=Kb[(j0+2)*65+d], b3=Kb[(j0+3)*65+d];
                float a0=qp0[dd], a1=qp1[dd], a2=qp2[dd], a3=qp3[dd];
                sacc[0][0]+=a0*b0; sacc[0][1]+=a0*b1; sacc[0][2]+=a0*b2; sacc[0][3]+=a0*b3;
                sacc[1][0]+=a1*b0; sacc[1][1]+=a1*b1; sacc[1][2]+=a1*b2; sacc[1][3]+=a1*b3;
                sacc[2][0]+=a2*b0; sacc[2][1]+=a2*b1; sacc[2][2]+=a2*b2; sacc[2][3]+=a2*b3;
                sacc[3][0]+=a3*b0; sacc[3][1]+=a3*b1; sacc[3][2]+=a3*b2; sacc[3][3]+=a3*b3;
            }
        }
        #pragma unroll
        for (int r = 0; r < 4; r++)
            #pragma unroll
            for (int c = 0; c < 4; c++)
                Sb[(i0+r)*64 + j0+c] = sacc[r][c];
    }
    __syncthreads();

    // overwrite Kb with V (float4, stride 17)
    {
        const float* Vg = g_V + (bh*TT + chunk*CH) * 64;
        for (int i = tid; i < 1024; i += 256) {
            int r = i >> 4, c4 = i & 15;
            Kb4[r*17 + c4] = ((const float4*)Vg)[i];
        }
    }
    __syncthreads();

    // phase 2: acc = tril(S) @ V
    const int e4 = g2;
    float acc[4][4] = {};
    for (int j = 0; j < 64; j++) {
        float4 b = Kb4[j*17 + e4];
        #pragma unroll
        for (int r = 0; r < 4; r++) {
            float sv = (j <= i0 + r) ? Sb[(i0+r)*64 + j] : 0.f;
            acc[r][0]+=sv*b.x; acc[r][1]+=sv*b.y; acc[r][2]+=sv*b.z; acc[r][3]+=sv*b.w;
        }
    }
    __syncthreads();

    // z-pass (threads 0..63) runs while all threads reload Kb with the prefix state
    const float* stg = g_kv + (bh*NCH + chunk) * 4096;
    const float* ksg = g_ks + (bh*NCH + chunk) * 64;
    float zreg = 0.f;
    if (tid < 64) {
        const int i = tid;
        for (int j = 0; j <= i; j++) zreg += Sb[i*64 + j];
        for (int d = 0; d < 64; d++) zreg += Qb[i*64 + d] * ksg[d];
    }
    for (int i = tid; i < 1024; i += 256) {
        int r = i >> 4, c4 = i & 15;
        Kb4[r*17 + c4] = ((const float4*)stg)[i];
    }
    if (tid < 64) Sb[tid] = zreg;
    __syncthreads();

    // phase 3: acc += phiQ @ state   (both float4; d ascending)
    for (int d4 = 0; d4 < 16; d4++) {
        float4 qa0 = Qb4[(i0+0)*16 + d4];
        float4 qa1 = Qb4[(i0+1)*16 + d4];
        float4 qa2 = Qb4[(i0+2)*16 + d4];
        float4 qa3 = Qb4[(i0+3)*16 + d4];
        const float* qp0 = (const float*)&qa0;
        const float* qp1 = (const float*)&qa1;
        const float* qp2 = (const float*)&qa2;
        const float* qp3 = (const float*)&qa3;
        #pragma unroll
        for (int dd = 0; dd < 4; dd++) {
            float4 b = Kb4[(d4*4+dd)*17 + e4];
            float a0=qp0[dd], a1=qp1[dd], a2=qp2[dd], a3=qp3[dd];
            acc[0][0]+=a0*b.x; acc[0][1]+=a0*b.y; acc[0][2]+=a0*b.z; acc[0][3]+=a0*b.w;
            acc[1][0]+=a1*b.x; acc[1][1]+=a1*b.y; acc[1][2]+=a1*b.z; acc[1][3]+=a1*b.w;
            acc[2][0]+=a2*b.x; acc[2][1]+=a2*b.y; acc[2][2]+=a2*b.z; acc[2][3]+=a2*b.w;
            acc[3][0]+=a3*b.x; acc[3][1]+=a3*b.y; acc[3][2]+=a3*b.z; acc[3][3]+=a3*b.w;
        }
    }

    // normalized output -> exact 3-way bf16 split, written directly
    const int b = bh >> 3, h = bh & 7;
    const int e0 = g2 * 4;
    #pragma unroll
    for (int r = 0; r < 4; r++) {
        const int t = chunk*CH + i0 + r;
        const float z = fmaxf(Sb[i0 + r], 1e-6f);
        #pragma unroll
        for (int c = 0; c < 4; c++) {
            float o = __fdiv_rn(acc[r][c], z);
            size_t idx = ((size_t)(b*TT + t)) * DM + h*64 + e0 + c;
            __nv_bfloat16 h1 = __float2bfloat16_rn(o);
            float r1 = o - __bfloat162float(h1);
            __nv_bfloat16 h2 = __float2bfloat16_rn(r1);
            float r2 = r1 - __bfloat162float(h2);
            g_as[idx]           = h1;
            g_as[idx + 1048576] = h2;
            g_as[idx + 2097152] = __float2bfloat16_rn(r2);
        }
    }
}

// ---------------- launch ----------------
extern "C" void kernel_launch(void* const* d_in, const int* in_sizes, int n_in,
                              void* d_out, int out_size)
{
    const float* x   = (const float*)d_in[0];
    const float* Wq  = (const float*)d_in[1];
    const float* Wk  = (const float*)d_in[2];
    const float* Wv  = (const float*)d_in[3];
    const float* Wo  = (const float*)d_in[4];
    const float* bo  = (const float*)d_in[5];
    const float* phi = (const float*)d_in[6];
    float* out = (float*)d_out;

    const int attn_smem = (4096 + 4352 + 4096) * sizeof(float);    // 50176
    const int mma_smem  = 2048 + 3 * 32768;                        // 100352
    cudaFuncSetAttribute(attn_kernel, cudaFuncAttributeMaxDynamicSharedMemorySize, attn_smem);
    cudaFuncSetAttribute(mma_gemm_kernel, cudaFuncAttributeMaxDynamicSharedMemorySize, mma_smem);

    void* alpha_addr = nullptr;
    cudaGetSymbolAddress(&alpha_addr, g_alpha);
    cudaMemsetAsync(alpha_addr, 0, 4 * sizeof(float));

    scales_part_kernel<<<64, 256>>>(Wq, Wk, Wv, Wo);
    scales_fin_kernel<<<1, 32>>>();
    conv_kernel<<<8192, 256>>>(x, Wq, Wk, Wv, Wo);
    mma_gemm_kernel<<<dim3(12, 16), 256, mma_smem>>>(nullptr, phi, nullptr, 0, 4);
    chunksum_kernel<<<dim3(NCH, BH), 256>>>();
    prefix_kernel<<<dim3(17, BH), 256>>>();
    attn_kernel<<<dim3(NCH, BH), 256, attn_smem>>>();
    mma_gemm_kernel<<<dim3(4, 32), 256, mma_smem>>>(bo, nullptr, out, 1, 2);
}

// round 7
// speedup vs baseline: 2.2150x; 1.0677x over previous
#include <cuda_runtime.h>
#include <cuda_bf16.h>
#include <math.h>
#include <stdint.h>

#define DM 512
#define TT 1024
#define BB 2
#define NH 8
#define BH 16      // BB*NH
#define CH 64      // chunk length
#define NCH 16     // TT/CH

// ---------------- scratch (device globals; no allocations) ----------------
__device__ float g_alpha[4];
__device__ float g_s[4];
__device__ float g_si[4];
__device__ float g_phiQ[BH*TT*64];          // (b,h,t,d)
__device__ float g_phiK[BH*TT*64];
__device__ float g_V  [BH*TT*64];
__device__ float g_kv [BH*NCH*64*64];
__device__ float g_ks [BH*NCH*64];
__device__ __nv_bfloat16 g_wt[4*512*512];   // ternary weights in bf16 (exact), [mat][n][k]
__device__ __nv_bfloat16 g_xs[3*2048*512];  // 3-way bf16 split of x
__device__ __nv_bfloat16 g_as[3*2048*512];  // 3-way bf16 split of attention output

// byte-offset swizzle within a 1KB atom (Swizzle<3,4,3>)
#define SWZ(o) ((o) ^ ((((o) >> 7) & 7) << 4))

__device__ __forceinline__ uint32_t smem_u32(const void* p) {
    uint32_t a;
    asm("{ .reg .u64 t; cvta.to.shared.u64 t, %1; cvt.u32.u64 %0, t; }" : "=r"(a) : "l"(p));
    return a;
}
__device__ __forceinline__ void ldmx4(uint32_t* r, uint32_t addr) {
    asm volatile("ldmatrix.sync.aligned.m8n8.x4.shared.b16 {%0,%1,%2,%3}, [%4];"
                 : "=r"(r[0]), "=r"(r[1]), "=r"(r[2]), "=r"(r[3]) : "r"(addr));
}
__device__ __forceinline__ void mma16816(float* c, const uint32_t* a, const uint32_t* b) {
    asm volatile("mma.sync.aligned.m16n8k16.row.col.f32.bf16.bf16.f32 "
                 "{%0,%1,%2,%3},{%4,%5,%6,%7},{%8,%9},{%0,%1,%2,%3};"
                 : "+f"(c[0]), "+f"(c[1]), "+f"(c[2]), "+f"(c[3])
                 : "r"(a[0]), "r"(a[1]), "r"(a[2]), "r"(a[3]), "r"(b[0]), "r"(b[1]));
}
#define CP16(dst, src)  asm volatile("cp.async.cg.shared.global [%0], [%1], 16;" :: "r"(dst), "l"(src))
#define CP_COMMIT()     asm volatile("cp.async.commit_group;" ::: "memory")
#define CP_WAIT1()      asm volatile("cp.async.wait_group 1;" ::: "memory")

// ---------------- 1a) ternary scale partial |W| sums ----------------
__global__ void scales_part_kernel(const float* __restrict__ Wq, const float* __restrict__ Wk,
                                   const float* __restrict__ Wv, const float* __restrict__ Wo)
{
    const int mat = blockIdx.x >> 4;             // 16 blocks per matrix
    const float* W = mat==0?Wq: mat==1?Wk: mat==2?Wv:Wo;
    const float4* W4 = (const float4*)(W + (blockIdx.x & 15) * 16384);
    float a = 0.f;
    #pragma unroll 4
    for (int i = threadIdx.x; i < 4096; i += 256) {
        float4 v = W4[i];
        a += fabsf(v.x) + fabsf(v.y) + fabsf(v.z) + fabsf(v.w);
    }
    __shared__ float red[256];
    red[threadIdx.x] = a; __syncthreads();
    for (int o = 128; o > 0; o >>= 1) {
        if (threadIdx.x < o) red[threadIdx.x] += red[threadIdx.x + o];
        __syncthreads();
    }
    if (threadIdx.x == 0) atomicAdd(&g_alpha[mat], red[0]);
}

// ---------------- 1b) finalize scales ----------------
__global__ void scales_fin_kernel()
{
    int t = threadIdx.x;
    if (t < 4) {
        float alpha = g_alpha[t] * (1.0f/(DM*DM)) + 1e-12f;
        float e = rintf(log2f(alpha));
        e = fminf(fmaxf(e, -4.f), 4.f);
        g_s [t] = exp2f(e);
        g_si[t] = exp2f(-e);
    }
}

// ---------------- 2) fused: weights->ternary bf16  +  3-way exact split of x ----------------
__global__ void conv_kernel(const float* __restrict__ xin,
                            const float* __restrict__ Wq, const float* __restrict__ Wk,
                            const float* __restrict__ Wv, const float* __restrict__ Wo)
{
    int bid = blockIdx.x;
    if (bid < 4096) {
        int i = bid * 256 + threadIdx.x;
        int mat = i >> 18;
        const float* W = mat==0?Wq: mat==1?Wk: mat==2?Wv:Wo;
        float v = W[i & 262143];
        float t = fminf(fmaxf(rintf(v * g_si[mat]), -1.f), 1.f) * g_s[mat];
        g_wt[i] = __float2bfloat16_rn(t);
    } else {
        int i = (bid - 4096) * 256 + threadIdx.x;
        float v = xin[i];
        __nv_bfloat16 h1 = __float2bfloat16_rn(v);
        float r1 = v - __bfloat162float(h1);
        __nv_bfloat16 h2 = __float2bfloat16_rn(r1);
        float r2 = r1 - __bfloat162float(h2);
        g_xs[i] = h1; g_xs[i + 1048576] = h2; g_xs[i + 2097152] = __float2bfloat16_rn(r2);
    }
}

// ---------------- 3) HMMA GEMM with cp.async 3-stage pipeline ----------------
// dyn smem: tbl 2KB @0 | stage s: A 16KB + B 16KB @ 2048 + s*32768   (total 100352 B)
// mtiles: 4 -> 128-row tile (QKV), 2 -> 64-row tile (O-proj)
extern __shared__ char DSM[];
__global__ __launch_bounds__(256, 2) void mma_gemm_kernel(
    const float* __restrict__ bias, const float* __restrict__ phi_table,
    float* __restrict__ Out, int mode, int mtiles)
{
    float* tbl = (float*)DSM;
    const uint32_t sbase = smem_u32(DSM);

    const int tid = threadIdx.x;
    const int wid = tid >> 5, lane = tid & 31;
    const int wm = wid >> 2, wn = wid & 3;       // 2 x 4 warp grid

    if (mode == 0) { tbl[tid] = phi_table[tid]; tbl[tid+256] = phi_table[tid+256]; }

    const int m0  = blockIdx.y * (mtiles * 32);
    const int n0g = blockIdx.x * 128;
    const int mat = (mode == 0) ? (n0g >> 9) : 3;
    const int nb0 = (mode == 0) ? (n0g & 511) : n0g;

    const __nv_bfloat16* Aall = (mode == 0) ? g_xs : g_as;
    const __nv_bfloat16* Wbase = g_wt + (size_t)(mat * 512 + nb0) * 512;

    // per-thread cp.async coords: chunks of 16B (A: mtiles per thread, B: 4)
    int lrow[4], lcol[4];
    #pragma unroll
    for (int i = 0; i < 4; i++) { int c = i*256 + tid; lrow[i] = c >> 3; lcol[i] = c & 7; }
    uint32_t swoff[4];
    #pragma unroll
    for (int i = 0; i < 4; i++) {
        uint32_t off = (uint32_t)lrow[i] * 128 + lcol[i] * 16;
        swoff[i] = SWZ(off);
    }

    float acc[4][4][4];
    #pragma unroll
    for (int i = 0; i < 4; i++)
        #pragma unroll
        for (int j = 0; j < 4; j++)
            #pragma unroll
            for (int k = 0; k < 4; k++) acc[i][j][k] = 0.f;

    // ldmatrix fragment offsets (within a stage), +ks*32 per k-step, then SWZ
    const int t16 = lane & 15;
    uint32_t a_off[4];
    #pragma unroll
    for (int i = 0; i < 4; i++)
        a_off[i] = (uint32_t)(wm*(mtiles*16) + i*16 + t16) * 128 + (lane >> 4) * 16;
    // B x4 offsets: pair j2 covers n-tiles {2*j2, 2*j2+1}; lane groups 0-7/8-15 = ntile 2j2
    // k-low/k-high, 16-23/24-31 = ntile 2j2+1 k-low/k-high
    uint32_t b4_off[2];
    #pragma unroll
    for (int j2 = 0; j2 < 2; j2++)
        b4_off[j2] = (uint32_t)(wn*32 + j2*16 + ((lane >> 4) << 3) + (lane & 7)) * 128
                   + (((lane >> 3) & 1) * 16);

    const int NP = 24;                            // 3 splits x 8 k-panels

    // panel issue: global -> smem stage (p % 3) via cp.async
    auto issue = [&](int p) {
        if (p < NP) {
            int split = p >> 3, kp = (p & 7) * 64;
            const __nv_bfloat16* Ab = Aall + (size_t)split * 1048576 + kp;
            const __nv_bfloat16* Bb = Wbase + kp;
            uint32_t bufA = sbase + 2048 + (uint32_t)(p % 3) * 32768;
            uint32_t bufB = bufA + 16384;
            #pragma unroll
            for (int i = 0; i < 4; i++) {
                if (i < mtiles)
                    CP16(bufA + swoff[i], Ab + (size_t)(m0 + lrow[i]) * 512 + lcol[i] * 8);
                CP16(bufB + swoff[i], Bb + (size_t)lrow[i] * 512 + lcol[i] * 8);
            }
        }
        CP_COMMIT();
    };

    issue(0); issue(1);

    #pragma unroll 1
    for (int p = 0; p < NP; p++) {
        CP_WAIT1();
        __syncthreads();
        issue(p + 2);                             // overwrites stage (p-1)%3 — all readers past barrier

        const uint32_t sA = sbase + 2048 + (uint32_t)(p % 3) * 32768;
        const uint32_t sB = sA + 16384;
        #pragma unroll
        for (int ks = 0; ks < 4; ks++) {
            uint32_t bf[8];                       // 4 n-tiles x {k-low, k-high}
            ldmx4(bf + 0, sB + SWZ(b4_off[0] + ks*32));
            ldmx4(bf + 4, sB + SWZ(b4_off[1] + ks*32));
            #pragma unroll
            for (int i = 0; i < 4; i++) {
                if (i < mtiles) {
                    uint32_t af[4];
                    ldmx4(af, sA + SWZ(a_off[i] + ks*32));
                    #pragma unroll
                    for (int j = 0; j < 4; j++)
                        mma16816(acc[i][j], af, bf + j*2);
                }
            }
        }
    }
    __syncthreads();

    // ---------------- epilogue ----------------
    const int lr4 = lane >> 2, lc2 = (lane & 3) * 2;
    if (mode == 0) {
        float* dst = (mat == 0) ? g_phiQ : (mat == 1) ? g_phiK : g_V;
        #pragma unroll
        for (int i = 0; i < 4; i++) {
            #pragma unroll
            for (int half = 0; half < 2; half++) {
                int m = m0 + wm*64 + i*16 + lr4 + half*8;
                int b = m >> 10, t = m & 1023;
                #pragma unroll
                for (int j = 0; j < 4; j++) {
                    int nc = nb0 + wn*32 + j*8 + lc2;
                    float v0 = acc[i][j][half*2+0];
                    float v1 = acc[i][j][half*2+1];
                    if (mat < 2) {
                        int i00 = min(max((int)rintf(__fdiv_rn(v0, 0.1f)) + 128, 0), 255);
                        int i01 = min(max((int)rintf(__fdiv_rn(v0, 0.2f)) + 128, 0), 255);
                        int i10 = min(max((int)rintf(__fdiv_rn(v1, 0.1f)) + 128, 0), 255);
                        int i11 = min(max((int)rintf(__fdiv_rn(v1, 0.2f)) + 128, 0), 255);
                        v0 = tbl[i00] + tbl[256 + i01];
                        v1 = tbl[i10] + tbl[256 + i11];
                    }
                    size_t base = ((size_t)((b << 3) + (nc >> 6)) * 1024 + t) * 64 + (nc & 63);
                    dst[base] = v0;
                    dst[base + 1] = v1;
                }
            }
        }
    } else {
        #pragma unroll
        for (int i = 0; i < 4; i++) {
            if (i < mtiles) {
                #pragma unroll
                for (int half = 0; half < 2; half++) {
                    int m = m0 + wm*(mtiles*16) + i*16 + lr4 + half*8;
                    #pragma unroll
                    for (int j = 0; j < 4; j++) {
                        int n = n0g + wn*32 + j*8 + lc2;
                        Out[(size_t)m * 512 + n]     = acc[i][j][half*2+0] + bias[n];
                        Out[(size_t)m * 512 + n + 1] = acc[i][j][half*2+1] + bias[n+1];
                    }
                }
            }
        }
    }
}

// ---------------- 4) per-chunk K^T V and K colsum (float4 smem reads) ----------------
__global__ __launch_bounds__(256) void chunksum_kernel()
{
    const int chunk = blockIdx.x, bh = blockIdx.y;
    __shared__ float Kt[CH*64];
    __shared__ float Vt[CH*64];
    const int tid = threadIdx.x;
    const float* Kg = g_phiK + (bh*TT + chunk*CH) * 64;
    const float* Vg = g_V    + (bh*TT + chunk*CH) * 64;
    for (int i = tid; i < CH*16; i += 256) {
        ((float4*)Kt)[i] = ((const float4*)Kg)[i];
        ((float4*)Vt)[i] = ((const float4*)Vg)[i];
    }
    __syncthreads();
    const int d4 = tid >> 4, e4 = tid & 15;      // float4 indices
    const float4* Kt4 = (const float4*)Kt;
    const float4* Vt4 = (const float4*)Vt;
    float acc[4][4] = {};
    #pragma unroll 4
    for (int t = 0; t < CH; t++) {
        float4 a = Kt4[t*16 + d4];
        float4 b = Vt4[t*16 + e4];
        acc[0][0]+=a.x*b.x; acc[0][1]+=a.x*b.y; acc[0][2]+=a.x*b.z; acc[0][3]+=a.x*b.w;
        acc[1][0]+=a.y*b.x; acc[1][1]+=a.y*b.y; acc[1][2]+=a.y*b.z; acc[1][3]+=a.y*b.w;
        acc[2][0]+=a.z*b.x; acc[2][1]+=a.z*b.y; acc[2][2]+=a.z*b.z; acc[2][3]+=a.z*b.w;
        acc[3][0]+=a.w*b.x; acc[3][1]+=a.w*b.y; acc[3][2]+=a.w*b.z; acc[3][3]+=a.w*b.w;
    }
    float* kvo = g_kv + (bh*NCH + chunk) * 4096;
    #pragma unroll
    for (int r = 0; r < 4; r++) {
        float4 o = make_float4(acc[r][0], acc[r][1], acc[r][2], acc[r][3]);
        *(float4*)(kvo + (d4*4+r)*64 + e4*4) = o;
    }
    if (tid < 64) {
        float su = 0.f;
        for (int t = 0; t < CH; t++) su += Kt[t*64 + tid];
        g_ks[(bh*NCH + chunk)*64 + tid] = su;
    }
}

// ---------------- 5) exclusive prefix over chunks (float4, MLP=16) ----------------
__global__ void prefix_kernel()
{
    const int bh = blockIdx.y;
    const int e = blockIdx.x * 256 + threadIdx.x;   // float4 index
    if (e < 1024) {
        float4* base = (float4*)(g_kv + bh*NCH*4096) + e;
        float4 v[NCH];
        #pragma unroll
        for (int c = 0; c < NCH; c++) v[c] = base[c*1024];   // MLP=16 burst
        float4 run = make_float4(0.f, 0.f, 0.f, 0.f);
        #pragma unroll
        for (int c = 0; c < NCH; c++) {
            float4 t = v[c];
            base[c*1024] = run;
            run.x += t.x; run.y += t.y; run.z += t.z; run.w += t.w;
        }
    } else if (e < 1024 + 16) {
        const int d = e - 1024;
        float4* base = (float4*)(g_ks + bh*NCH*64) + d;
        float4 v[NCH];
        #pragma unroll
        for (int c = 0; c < NCH; c++) v[c] = base[c*16];
        float4 run = make_float4(0.f, 0.f, 0.f, 0.f);
        #pragma unroll
        for (int c = 0; c < NCH; c++) {
            float4 t = v[c];
            base[c*16] = run;
            run.x += t.x; run.y += t.y; run.z += t.z; run.w += t.w;
        }
    }
}

// ---------------- 6) chunked causal attention + fused bf16-split epilogue ----------------
// dyn smem: Qb[4096] | Kb[64*68=4352] | Sb[4096]  floats = 50176 B
__global__ __launch_bounds__(256) void attn_kernel()
{
    float* dsm = (float*)DSM;
    const int chunk = blockIdx.x, bh = blockIdx.y;
    float* Qb = dsm;
    float* Kb = dsm + 4096;
    float* Sb = dsm + 4096 + 4352;
    float4* Qb4 = (float4*)Qb;
    float4* Kb4 = (float4*)Kb;                   // stride 17 float4s (68 floats) for V/state
    const int tid = threadIdx.x;

    const float* Qg = g_phiQ + (bh*TT + chunk*CH) * 64;
    const float* Kg = g_phiK + (bh*TT + chunk*CH) * 64;
    for (int i = tid; i < 1024; i += 256) Qb4[i] = ((const float4*)Qg)[i];
    for (int i = tid; i < 1024; i += 256) {      // K row-major stride 65 (phase-1 layout)
        int r = i >> 4, cc = (i & 15) << 2;
        float4 v = ((const float4*)Kg)[i];
        Kb[r*65+cc+0]=v.x; Kb[r*65+cc+1]=v.y; Kb[r*65+cc+2]=v.z; Kb[r*65+cc+3]=v.w;
    }
    __syncthreads();

    const int g1 = tid >> 4, g2 = tid & 15;
    const int i0 = g1 * 4;

    // phase 1: S = phiQ @ phiK^T   (Qb via float4, Kb scalar stride-65; d ascending)
    {
        const int j0 = g2 * 4;
        float sacc[4][4] = {};
        for (int d4 = 0; d4 < 16; d4++) {
            float4 qa0 = Qb4[(i0+0)*16 + d4];
            float4 qa1 = Qb4[(i0+1)*16 + d4];
            float4 qa2 = Qb4[(i0+2)*16 + d4];
            float4 qa3 = Qb4[(i0+3)*16 + d4];
            const float* qp0 = (const float*)&qa0;
            const float* qp1 = (const float*)&qa1;
            const float* qp2 = (const float*)&qa2;
            const float* qp3 = (const float*)&qa3;
            #pragma unroll
            for (int dd = 0; dd < 4; dd++) {
                int d = d4*4 + dd;
                float b0=Kb[(j0+0)*65+d], b1=Kb[(j0+1)*65+d], b2=Kb[(j0+2)*65+d], b3=Kb[(j0+3)*65+d];
                float a0=qp0[dd], a1=qp1[dd], a2=qp2[dd], a3=qp3[dd];
                sacc[0][0]+=a0*b0; sacc[0][1]+=a0*b1; sacc[0][2]+=a0*b2; sacc[0][3]+=a0*b3;
                sacc[1][0]+=a1*b0; sacc[1][1]+=a1*b1; sacc[1][2]+=a1*b2; sacc[1][3]+=a1*b3;
                sacc[2][0]+=a2*b0; sacc[2][1]+=a2*b1; sacc[2][2]+=a2*b2; sacc[2][3]+=a2*b3;
                sacc[3][0]+=a3*b0; sacc[3][1]+=a3*b1; sacc[3][2]+=a3*b2; sacc[3][3]+=a3*b3;
            }
        }
        #pragma unroll
        for (int r = 0; r < 4; r++)
            #pragma unroll
            for (int c = 0; c < 4; c++)
                Sb[(i0+r)*64 + j0+c] = sacc[r][c];
    }
    __syncthreads();

    // overwrite Kb with V (float4, stride 17)
    {
        const float* Vg = g_V + (bh*TT + chunk*CH) * 64;
        for (int i = tid; i < 1024; i += 256) {
            int r = i >> 4, c4 = i & 15;
            Kb4[r*17 + c4] = ((const float4*)Vg)[i];
        }
    }
    __syncthreads();

    // phase 2: acc = tril(S) @ V
    const int e4 = g2;
    float acc[4][4] = {};
    for (int j = 0; j < 64; j++) {
        float4 b = Kb4[j*17 + e4];
        #pragma unroll
        for (int r = 0; r < 4; r++) {
            float sv = (j <= i0 + r) ? Sb[(i0+r)*64 + j] : 0.f;
            acc[r][0]+=sv*b.x; acc[r][1]+=sv*b.y; acc[r][2]+=sv*b.z; acc[r][3]+=sv*b.w;
        }
    }
    __syncthreads();

    // z-pass (threads 0..63) runs while all threads reload Kb with the prefix state
    const float* stg = g_kv + (bh*NCH + chunk) * 4096;
    const float* ksg = g_ks + (bh*NCH + chunk) * 64;
    float zreg = 0.f;
    if (tid < 64) {
        const int i = tid;
        for (int j = 0; j <= i; j++) zreg += Sb[i*64 + j];
        for (int d = 0; d < 64; d++) zreg += Qb[i*64 + d] * ksg[d];
    }
    for (int i = tid; i < 1024; i += 256) {
        int r = i >> 4, c4 = i & 15;
        Kb4[r*17 + c4] = ((const float4*)stg)[i];
    }
    if (tid < 64) Sb[tid] = zreg;
    __syncthreads();

    // phase 3: acc += phiQ @ state   (both float4; d ascending)
    for (int d4 = 0; d4 < 16; d4++) {
        float4 qa0 = Qb4[(i0+0)*16 + d4];
        float4 qa1 = Qb4[(i0+1)*16 + d4];
        float4 qa2 = Qb4[(i0+2)*16 + d4];
        float4 qa3 = Qb4[(i0+3)*16 + d4];
        const float* qp0 = (const float*)&qa0;
        const float* qp1 = (const float*)&qa1;
        const float* qp2 = (const float*)&qa2;
        const float* qp3 = (const float*)&qa3;
        #pragma unroll
        for (int dd = 0; dd < 4; dd++) {
            float4 b = Kb4[(d4*4+dd)*17 + e4];
            float a0=qp0[dd], a1=qp1[dd], a2=qp2[dd], a3=qp3[dd];
            acc[0][0]+=a0*b.x; acc[0][1]+=a0*b.y; acc[0][2]+=a0*b.z; acc[0][3]+=a0*b.w;
            acc[1][0]+=a1*b.x; acc[1][1]+=a1*b.y; acc[1][2]+=a1*b.z; acc[1][3]+=a1*b.w;
            acc[2][0]+=a2*b.x; acc[2][1]+=a2*b.y; acc[2][2]+=a2*b.z; acc[2][3]+=a2*b.w;
            acc[3][0]+=a3*b.x; acc[3][1]+=a3*b.y; acc[3][2]+=a3*b.z; acc[3][3]+=a3*b.w;
        }
    }

    // normalized output -> exact 3-way bf16 split, written directly
    const int b = bh >> 3, h = bh & 7;
    const int e0 = g2 * 4;
    #pragma unroll
    for (int r = 0; r < 4; r++) {
        const int t = chunk*CH + i0 + r;
        const float z = fmaxf(Sb[i0 + r], 1e-6f);
        #pragma unroll
        for (int c = 0; c < 4; c++) {
            float o = __fdiv_rn(acc[r][c], z);
            size_t idx = ((size_t)(b*TT + t)) * DM + h*64 + e0 + c;
            __nv_bfloat16 h1 = __float2bfloat16_rn(o);
            float r1 = o - __bfloat162float(h1);
            __nv_bfloat16 h2 = __float2bfloat16_rn(r1);
            float r2 = r1 - __bfloat162float(h2);
            g_as[idx]           = h1;
            g_as[idx + 1048576] = h2;
            g_as[idx + 2097152] = __float2bfloat16_rn(r2);
        }
    }
}

// ---------------- launch ----------------
extern "C" void kernel_launch(void* const* d_in, const int* in_sizes, int n_in,
                              void* d_out, int out_size)
{
    const float* x   = (const float*)d_in[0];
    const float* Wq  = (const float*)d_in[1];
    const float* Wk  = (const float*)d_in[2];
    const float* Wv  = (const float*)d_in[3];
    const float* Wo  = (const float*)d_in[4];
    const float* bo  = (const float*)d_in[5];
    const float* phi = (const float*)d_in[6];
    float* out = (float*)d_out;

    const int attn_smem = (4096 + 4352 + 4096) * sizeof(float);    // 50176
    const int mma_smem  = 2048 + 3 * 32768;                        // 100352
    cudaFuncSetAttribute(attn_kernel, cudaFuncAttributeMaxDynamicSharedMemorySize, attn_smem);
    cudaFuncSetAttribute(mma_gemm_kernel, cudaFuncAttributeMaxDynamicSharedMemorySize, mma_smem);

    void* alpha_addr = nullptr;
    cudaGetSymbolAddress(&alpha_addr, g_alpha);
    cudaMemsetAsync(alpha_addr, 0, 4 * sizeof(float));

    scales_part_kernel<<<64, 256>>>(Wq, Wk, Wv, Wo);
    scales_fin_kernel<<<1, 32>>>();
    conv_kernel<<<8192, 256>>>(x, Wq, Wk, Wv, Wo);
    mma_gemm_kernel<<<dim3(12, 16), 256, mma_smem>>>(nullptr, phi, nullptr, 0, 4);
    chunksum_kernel<<<dim3(NCH, BH), 256>>>();
    prefix_kernel<<<dim3(5, BH), 256>>>();
    attn_kernel<<<dim3(NCH, BH), 256, attn_smem>>>();
    mma_gemm_kernel<<<dim3(4, 32), 256, mma_smem>>>(bo, nullptr, out, 1, 2);
}

// round 9
// speedup vs baseline: 2.5628x; 1.1570x over previous
#include <cuda_runtime.h>
#include <cuda_bf16.h>
#include <math.h>
#include <stdint.h>

#define DM 512
#define TT 1024
#define BB 2
#define NH 8
#define BH 16      // BB*NH
#define CH 64      // chunk length
#define NCH 16     // TT/CH

// ---------------- scratch (device globals; no allocations) ----------------
__device__ float g_alpha[4];
__device__ float g_s[4];
__device__ float g_si[4];
__device__ float g_phiQ[BH*TT*64];          // (b,h,t,d)
__device__ float g_phiK[BH*TT*64];
__device__ float g_V  [BH*TT*64];
__device__ float g_kv [BH*NCH*64*64];
__device__ float g_ks [BH*NCH*64];
__device__ __nv_bfloat16 g_wt[4*512*512];   // ternary weights in bf16 (exact), [mat][n][k]
__device__ __nv_bfloat16 g_xs[3*2048*512];  // 3-way bf16 split of x
__device__ __nv_bfloat16 g_as[3*2048*512];  // 3-way bf16 split of attention output

// byte-offset swizzle within a 1KB atom (Swizzle<3,4,3>)
#define SWZ(o) ((o) ^ ((((o) >> 7) & 7) << 4))

__device__ __forceinline__ uint32_t smem_u32(const void* p) {
    uint32_t a;
    asm("{ .reg .u64 t; cvta.to.shared.u64 t, %1; cvt.u32.u64 %0, t; }" : "=r"(a) : "l"(p));
    return a;
}
__device__ __forceinline__ void ldmx4(uint32_t* r, uint32_t addr) {
    asm volatile("ldmatrix.sync.aligned.m8n8.x4.shared.b16 {%0,%1,%2,%3}, [%4];"
                 : "=r"(r[0]), "=r"(r[1]), "=r"(r[2]), "=r"(r[3]) : "r"(addr));
}
__device__ __forceinline__ void mma16816(float* c, const uint32_t* a, const uint32_t* b) {
    asm volatile("mma.sync.aligned.m16n8k16.row.col.f32.bf16.bf16.f32 "
                 "{%0,%1,%2,%3},{%4,%5,%6,%7},{%8,%9},{%0,%1,%2,%3};"
                 : "+f"(c[0]), "+f"(c[1]), "+f"(c[2]), "+f"(c[3])
                 : "r"(a[0]), "r"(a[1]), "r"(a[2]), "r"(a[3]), "r"(b[0]), "r"(b[1]));
}
#define CP16(dst, src)  asm volatile("cp.async.cg.shared.global [%0], [%1], 16;" :: "r"(dst), "l"(src))
#define CP_COMMIT()     asm volatile("cp.async.commit_group;" ::: "memory")
#define CP_WAIT1()      asm volatile("cp.async.wait_group 1;" ::: "memory")

// ---------------- 1a) ternary scale partial |W| sums ----------------
__global__ void scales_part_kernel(const float* __restrict__ Wq, const float* __restrict__ Wk,
                                   const float* __restrict__ Wv, const float* __restrict__ Wo)
{
    const int mat = blockIdx.x >> 4;             // 16 blocks per matrix
    const float* W = mat==0?Wq: mat==1?Wk: mat==2?Wv:Wo;
    const float4* W4 = (const float4*)(W + (blockIdx.x & 15) * 16384);
    float a = 0.f;
    #pragma unroll 4
    for (int i = threadIdx.x; i < 4096; i += 256) {
        float4 v = W4[i];
        a += fabsf(v.x) + fabsf(v.y) + fabsf(v.z) + fabsf(v.w);
    }
    __shared__ float red[256];
    red[threadIdx.x] = a; __syncthreads();
    for (int o = 128; o > 0; o >>= 1) {
        if (threadIdx.x < o) red[threadIdx.x] += red[threadIdx.x + o];
        __syncthreads();
    }
    if (threadIdx.x == 0) atomicAdd(&g_alpha[mat], red[0]);
}

// ---------------- 1b) finalize scales ----------------
__global__ void scales_fin_kernel()
{
    int t = threadIdx.x;
    if (t < 4) {
        float alpha = g_alpha[t] * (1.0f/(DM*DM)) + 1e-12f;
        float e = rintf(log2f(alpha));
        e = fminf(fmaxf(e, -4.f), 4.f);
        g_s [t] = exp2f(e);
        g_si[t] = exp2f(-e);
    }
}

// ---------------- 2) fused: weights->ternary bf16  +  3-way exact split of x ----------------
__global__ void conv_kernel(const float* __restrict__ xin,
                            const float* __restrict__ Wq, const float* __restrict__ Wk,
                            const float* __restrict__ Wv, const float* __restrict__ Wo)
{
    int bid = blockIdx.x;
    if (bid < 4096) {
        int i = bid * 256 + threadIdx.x;
        int mat = i >> 18;
        const float* W = mat==0?Wq: mat==1?Wk: mat==2?Wv:Wo;
        float v = W[i & 262143];
        float t = fminf(fmaxf(rintf(v * g_si[mat]), -1.f), 1.f) * g_s[mat];
        g_wt[i] = __float2bfloat16_rn(t);
    } else {
        int i = (bid - 4096) * 256 + threadIdx.x;
        float v = xin[i];
        __nv_bfloat16 h1 = __float2bfloat16_rn(v);
        float r1 = v - __bfloat162float(h1);
        __nv_bfloat16 h2 = __float2bfloat16_rn(r1);
        float r2 = r1 - __bfloat162float(h2);
        g_xs[i] = h1; g_xs[i + 1048576] = h2; g_xs[i + 2097152] = __float2bfloat16_rn(r2);
    }
}

// ---------------- 3) HMMA GEMM, 64x128 tile, cp.async 3-stage, 3 CTAs/SM ----------------
// dyn smem: tbl 2KB @0 | stage s: A 8KB + B 16KB @ 2048 + s*24576   (total 75776 B)
extern __shared__ char DSM[];
__global__ __launch_bounds__(256, 3) void mma_gemm_kernel(
    const float* __restrict__ bias, const float* __restrict__ phi_table,
    float* __restrict__ Out, int mode)
{
    float* tbl = (float*)DSM;
    const uint32_t sbase = smem_u32(DSM);

    const int tid = threadIdx.x;
    const int wid = tid >> 5, lane = tid & 31;
    const int wm = wid >> 2, wn = wid & 3;       // 2 x 4 warp grid; warp tile 32x32

    if (mode == 0) { tbl[tid] = phi_table[tid]; tbl[tid+256] = phi_table[tid+256]; }

    const int m0  = blockIdx.y * 64;
    const int n0g = blockIdx.x * 128;
    const int mat = (mode == 0) ? (n0g >> 9) : 3;
    const int nb0 = (mode == 0) ? (n0g & 511) : n0g;

    const __nv_bfloat16* Aall = (mode == 0) ? g_xs : g_as;
    const __nv_bfloat16* Wbase = g_wt + (size_t)(mat * 512 + nb0) * 512;

    // per-thread cp.async coords: chunks of 16B (A: 2 per thread, B: 4)
    int lrow[4], lcol[4];
    #pragma unroll
    for (int i = 0; i < 4; i++) { int c = i*256 + tid; lrow[i] = c >> 3; lcol[i] = c & 7; }
    uint32_t swoff[4];
    #pragma unroll
    for (int i = 0; i < 4; i++) {
        uint32_t off = (uint32_t)lrow[i] * 128 + lcol[i] * 16;
        swoff[i] = SWZ(off);
    }

    float acc[2][4][4];
    #pragma unroll
    for (int i = 0; i < 2; i++)
        #pragma unroll
        for (int j = 0; j < 4; j++)
            #pragma unroll
            for (int k = 0; k < 4; k++) acc[i][j][k] = 0.f;

    // ldmatrix fragment offsets (within a stage), +ks*32 per k-step, then SWZ
    const int t16 = lane & 15;
    uint32_t a_off[2];
    #pragma unroll
    for (int i = 0; i < 2; i++)
        a_off[i] = (uint32_t)(wm*32 + i*16 + t16) * 128 + (lane >> 4) * 16;
    // B x4 offsets: pair j2 covers n-tiles {2*j2, 2*j2+1}
    uint32_t b4_off[2];
    #pragma unroll
    for (int j2 = 0; j2 < 2; j2++)
        b4_off[j2] = (uint32_t)(wn*32 + j2*16 + ((lane >> 4) << 3) + (lane & 7)) * 128
                   + (((lane >> 3) & 1) * 16);

    const int NP = 24;                            // 3 splits x 8 k-panels

    // panel issue: global -> smem stage (p % 3) via cp.async
    auto issue = [&](int p) {
        if (p < NP) {
            int split = p >> 3, kp = (p & 7) * 64;
            const __nv_bfloat16* Ab = Aall + (size_t)split * 1048576 + kp;
            const __nv_bfloat16* Bb = Wbase + kp;
            uint32_t bufA = sbase + 2048 + (uint32_t)(p % 3) * 24576;
            uint32_t bufB = bufA + 8192;
            #pragma unroll
            for (int i = 0; i < 4; i++) {
                if (i < 2)
                    CP16(bufA + swoff[i], Ab + (size_t)(m0 + lrow[i]) * 512 + lcol[i] * 8);
                CP16(bufB + swoff[i], Bb + (size_t)lrow[i] * 512 + lcol[i] * 8);
            }
        }
        CP_COMMIT();
    };

    issue(0); issue(1);

    #pragma unroll 1
    for (int p = 0; p < NP; p++) {
        CP_WAIT1();
        __syncthreads();
        issue(p + 2);                             // overwrites stage (p-1)%3 — all readers past barrier

        const uint32_t sA = sbase + 2048 + (uint32_t)(p % 3) * 24576;
        const uint32_t sB = sA + 8192;
        #pragma unroll
        for (int ks = 0; ks < 4; ks++) {
            uint32_t bf[8];                       // 4 n-tiles x {k-low, k-high}
            ldmx4(bf + 0, sB + SWZ(b4_off[0] + ks*32));
            ldmx4(bf + 4, sB + SWZ(b4_off[1] + ks*32));
            #pragma unroll
            for (int i = 0; i < 2; i++) {
                uint32_t af[4];
                ldmx4(af, sA + SWZ(a_off[i] + ks*32));
                #pragma unroll
                for (int j = 0; j < 4; j++)
                    mma16816(acc[i][j], af, bf + j*2);
            }
        }
    }
    __syncthreads();

    // ---------------- epilogue ----------------
    const int lr4 = lane >> 2, lc2 = (lane & 3) * 2;
    if (mode == 0) {
        float* dst = (mat == 0) ? g_phiQ : (mat == 1) ? g_phiK : g_V;
        #pragma unroll
        for (int i = 0; i < 2; i++) {
            #pragma unroll
            for (int half = 0; half < 2; half++) {
                int m = m0 + wm*32 + i*16 + lr4 + half*8;
                int b = m >> 10, t = m & 1023;
                #pragma unroll
                for (int j = 0; j < 4; j++) {
                    int nc = nb0 + wn*32 + j*8 + lc2;
                    float v0 = acc[i][j][half*2+0];
                    float v1 = acc[i][j][half*2+1];
                    if (mat < 2) {
                        int i00 = min(max((int)rintf(__fdiv_rn(v0, 0.1f)) + 128, 0), 255);
                        int i01 = min(max((int)rintf(__fdiv_rn(v0, 0.2f)) + 128, 0), 255);
                        int i10 = min(max((int)rintf(__fdiv_rn(v1, 0.1f)) + 128, 0), 255);
                        int i11 = min(max((int)rintf(__fdiv_rn(v1, 0.2f)) + 128, 0), 255);
                        v0 = tbl[i00] + tbl[256 + i01];
                        v1 = tbl[i10] + tbl[256 + i11];
                    }
                    size_t base = ((size_t)((b << 3) + (nc >> 6)) * 1024 + t) * 64 + (nc & 63);
                    dst[base] = v0;
                    dst[base + 1] = v1;
                }
            }
        }
    } else {
        #pragma unroll
        for (int i = 0; i < 2; i++) {
            #pragma unroll
            for (int half = 0; half < 2; half++) {
                int m = m0 + wm*32 + i*16 + lr4 + half*8;
                #pragma unroll
                for (int j = 0; j < 4; j++) {
                    int n = n0g + wn*32 + j*8 + lc2;
                    Out[(size_t)m * 512 + n]     = acc[i][j][half*2+0] + bias[n];
                    Out[(size_t)m * 512 + n + 1] = acc[i][j][half*2+1] + bias[n+1];
                }
            }
        }
    }
}

// ---------------- 4) per-chunk K^T V and K colsum (float4 smem reads) ----------------
__global__ __launch_bounds__(256) void chunksum_kernel()
{
    const int chunk = blockIdx.x, bh = blockIdx.y;
    __shared__ float Kt[CH*64];
    __shared__ float Vt[CH*64];
    const int tid = threadIdx.x;
    const float* Kg = g_phiK + (bh*TT + chunk*CH) * 64;
    const float* Vg = g_V    + (bh*TT + chunk*CH) * 64;
    for (int i = tid; i < CH*16; i += 256) {
        ((float4*)Kt)[i] = ((const float4*)Kg)[i];
        ((float4*)Vt)[i] = ((const float4*)Vg)[i];
    }
    __syncthreads();
    const int d4 = tid >> 4, e4 = tid & 15;      // float4 indices
    const float4* Kt4 = (const float4*)Kt;
    const float4* Vt4 = (const float4*)Vt;
    float acc[4][4] = {};
    #pragma unroll 4
    for (int t = 0; t < CH; t++) {
        float4 a = Kt4[t*16 + d4];
        float4 b = Vt4[t*16 + e4];
        acc[0][0]+=a.x*b.x; acc[0][1]+=a.x*b.y; acc[0][2]+=a.x*b.z; acc[0][3]+=a.x*b.w;
        acc[1][0]+=a.y*b.x; acc[1][1]+=a.y*b.y; acc[1][2]+=a.y*b.z; acc[1][3]+=a.y*b.w;
        acc[2][0]+=a.z*b.x; acc[2][1]+=a.z*b.y; acc[2][2]+=a.z*b.z; acc[2][3]+=a.z*b.w;
        acc[3][0]+=a.w*b.x; acc[3][1]+=a.w*b.y; acc[3][2]+=a.w*b.z; acc[3][3]+=a.w*b.w;
    }
    float* kvo = g_kv + (bh*NCH + chunk) * 4096;
    #pragma unroll
    for (int r = 0; r < 4; r++) {
        float4 o = make_float4(acc[r][0], acc[r][1], acc[r][2], acc[r][3]);
        *(float4*)(kvo + (d4*4+r)*64 + e4*4) = o;
    }
    if (tid < 64) {
        float su = 0.f;
        for (int t = 0; t < CH; t++) su += Kt[t*64 + tid];
        g_ks[(bh*NCH + chunk)*64 + tid] = su;
    }
}

// ---------------- 5) exclusive prefix over chunks (float4, MLP=16) ----------------
__global__ void prefix_kernel()
{
    const int bh = blockIdx.y;
    const int e = blockIdx.x * 256 + threadIdx.x;   // float4 index
    if (e < 1024) {
        float4* base = (float4*)(g_kv + bh*NCH*4096) + e;
        float4 v[NCH];
        #pragma unroll
        for (int c = 0; c < NCH; c++) v[c] = base[c*1024];   // MLP=16 burst
        float4 run = make_float4(0.f, 0.f, 0.f, 0.f);
        #pragma unroll
        for (int c = 0; c < NCH; c++) {
            float4 t = v[c];
            base[c*1024] = run;
            run.x += t.x; run.y += t.y; run.z += t.z; run.w += t.w;
        }
    } else if (e < 1024 + 16) {
        const int d = e - 1024;
        float4* base = (float4*)(g_ks + bh*NCH*64) + d;
        float4 v[NCH];
        #pragma unroll
        for (int c = 0; c < NCH; c++) v[c] = base[c*16];
        float4 run = make_float4(0.f, 0.f, 0.f, 0.f);
        #pragma unroll
        for (int c = 0; c < NCH; c++) {
            float4 t = v[c];
            base[c*16] = run;
            run.x += t.x; run.y += t.y; run.z += t.z; run.w += t.w;
        }
    }
}

// ---------------- 6) chunked causal attention + fused bf16-split epilogue ----------------
// dyn smem: Qb[4096] | Kb[64*68=4352] | Sb[4096]  floats = 50176 B
__global__ __launch_bounds__(256) void attn_kernel()
{
    float* dsm = (float*)DSM;
    const int chunk = blockIdx.x, bh = blockIdx.y;
    float* Qb = dsm;
    float* Kb = dsm + 4096;
    float* Sb = dsm + 4096 + 4352;
    float4* Qb4 = (float4*)Qb;
    float4* Kb4 = (float4*)Kb;                   // stride 17 float4s (68 floats) for V/state
    const int tid = threadIdx.x;

    const float* Qg = g_phiQ + (bh*TT + chunk*CH) * 64;
    const float* Kg = g_phiK + (bh*TT + chunk*CH) * 64;
    for (int i = tid; i < 1024; i += 256) Qb4[i] = ((const float4*)Qg)[i];
    for (int i = tid; i < 1024; i += 256) {      // K row-major stride 65 (phase-1 layout)
        int r = i >> 4, cc = (i & 15) << 2;
        float4 v = ((const float4*)Kg)[i];
        Kb[r*65+cc+0]=v.x; Kb[r*65+cc+1]=v.y; Kb[r*65+cc+2]=v.z; Kb[r*65+cc+3]=v.w;
    }
    __syncthreads();

    const int g1 = tid >> 4, g2 = tid & 15;
    const int i0 = g1 * 4;

    // phase 1: S = phiQ @ phiK^T   (Qb via float4, Kb scalar stride-65; d ascending)
    {
        const int j0 = g2 * 4;
        float sacc[4][4] = {};
        for (int d4 = 0; d4 < 16; d4++) {
            float4 qa0 = Qb4[(i0+0)*16 + d4];
            float4 qa1 = Qb4[(i0+1)*16 + d4];
            float4 qa2 = Qb4[(i0+2)*16 + d4];
            float4 qa3 = Qb4[(i0+3)*16 + d4];
            const float* qp0 = (const float*)&qa0;
            const float* qp1 = (const float*)&qa1;
            const float* qp2 = (const float*)&qa2;
            const float* qp3 = (const float*)&qa3;
            #pragma unroll
            for (int dd = 0; dd < 4; dd++) {
                int d = d4*4 + dd;
                float b0=Kb[(j0+0)*65+d], b1=Kb[(j0+1)*65+d], b2=Kb[(j0+2)*65+d], b3=Kb[(j0+3)*65+d];
                float a0=qp0[dd], a1=qp1[dd], a2=qp2[dd], a3=qp3[dd];
                sacc[0][0]+=a0*b0; sacc[0][1]+=a0*b1; sacc[0][2]+=a0*b2; sacc[0][3]+=a0*b3;
                sacc[1][0]+=a1*b0; sacc[1][1]+=a1*b1; sacc[1][2]+=a1*b2; sacc[1][3]+=a1*b3;
                sacc[2][0]+=a2*b0; sacc[2][1]+=a2*b1; sacc[2][2]+=a2*b2; sacc[2][3]+=a2*b3;
                sacc[3][0]+=a3*b0; sacc[3][1]+=a3*b1; sacc[3][2]+=a3*b2; sacc[3][3]+=a3*b3;
            }
        }
        #pragma unroll
        for (int r = 0; r < 4; r++)
            #pragma unroll
            for (int c = 0; c < 4; c++)
                Sb[(i0+r)*64 + j0+c] = sacc[r][c];
    }
    __syncthreads();

    // overwrite Kb with V (float4, stride 17)
    {
        const float* Vg = g_V + (bh*TT + chunk*CH) * 64;
        for (int i = tid; i < 1024; i += 256) {
            int r = i >> 4, c4 = i & 15;
            Kb4[r*17 + c4] = ((const float4*)Vg)[i];
        }
    }
    __syncthreads();

    // phase 2: acc = tril(S) @ V
    const int e4 = g2;
    float acc[4][4] = {};
    for (int j = 0; j < 64; j++) {
        float4 b = Kb4[j*17 + e4];
        #pragma unroll
        for (int r = 0; r < 4; r++) {
            float sv = (j <= i0 + r) ? Sb[(i0+r)*64 + j] : 0.f;
            acc[r][0]+=sv*b.x; acc[r][1]+=sv*b.y; acc[r][2]+=sv*b.z; acc[r][3]+=sv*b.w;
        }
    }
    __syncthreads();

    // z-pass (threads 0..63) runs while all threads reload Kb with the prefix state
    const float* stg = g_kv + (bh*NCH + chunk) * 4096;
    const float* ksg = g_ks + (bh*NCH + chunk) * 64;
    float zreg = 0.f;
    if (tid < 64) {
        const int i = tid;
        for (int j = 0; j <= i; j++) zreg += Sb[i*64 + j];
        for (int d = 0; d < 64; d++) zreg += Qb[i*64 + d] * ksg[d];
    }
    for (int i = tid; i < 1024; i += 256) {
        int r = i >> 4, c4 = i & 15;
        Kb4[r*17 + c4] = ((const float4*)stg)[i];
    }
    if (tid < 64) Sb[tid] = zreg;
    __syncthreads();

    // phase 3: acc += phiQ @ state   (both float4; d ascending)
    for (int d4 = 0; d4 < 16; d4++) {
        float4 qa0 = Qb4[(i0+0)*16 + d4];
        float4 qa1 = Qb4[(i0+1)*16 + d4];
        float4 qa2 = Qb4[(i0+2)*16 + d4];
        float4 qa3 = Qb4[(i0+3)*16 + d4];
        const float* qp0 = (const float*)&qa0;
        const float* qp1 = (const float*)&qa1;
        const float* qp2 = (const float*)&qa2;
        const float* qp3 = (const float*)&qa3;
        #pragma unroll
        for (int dd = 0; dd < 4; dd++) {
            float4 b = Kb4[(d4*4+dd)*17 + e4];
            float a0=qp0[dd], a1=qp1[dd], a2=qp2[dd], a3=qp3[dd];
            acc[0][0]+=a0*b.x; acc[0][1]+=a0*b.y; acc[0][2]+=a0*b.z; acc[0][3]+=a0*b.w;
            acc[1][0]+=a1*b.x; acc[1][1]+=a1*b.y; acc[1][2]+=a1*b.z; acc[1][3]+=a1*b.w;
            acc[2][0]+=a2*b.x; acc[2][1]+=a2*b.y; acc[2][2]+=a2*b.z; acc[2][3]+=a2*b.w;
            acc[3][0]+=a3*b.x; acc[3][1]+=a3*b.y; acc[3][2]+=a3*b.z; acc[3][3]+=a3*b.w;
        }
    }

    // normalized output -> exact 3-way bf16 split, written directly
    const int b = bh >> 3, h = bh & 7;
    const int e0 = g2 * 4;
    #pragma unroll
    for (int r = 0; r < 4; r++) {
        const int t = chunk*CH + i0 + r;
        const float z = fmaxf(Sb[i0 + r], 1e-6f);
        #pragma unroll
        for (int c = 0; c < 4; c++) {
            float o = __fdiv_rn(acc[r][c], z);
            size_t idx = ((size_t)(b*TT + t)) * DM + h*64 + e0 + c;
            __nv_bfloat16 h1 = __float2bfloat16_rn(o);
            float r1 = o - __bfloat162float(h1);
            __nv_bfloat16 h2 = __float2bfloat16_rn(r1);
            float r2 = r1 - __bfloat162float(h2);
            g_as[idx]           = h1;
            g_as[idx + 1048576] = h2;
            g_as[idx + 2097152] = __float2bfloat16_rn(r2);
        }
    }
}

// ---------------- launch ----------------
extern "C" void kernel_launch(void* const* d_in, const int* in_sizes, int n_in,
                              void* d_out, int out_size)
{
    const float* x   = (const float*)d_in[0];
    const float* Wq  = (const float*)d_in[1];
    const float* Wk  = (const float*)d_in[2];
    const float* Wv  = (const float*)d_in[3];
    const float* Wo  = (const float*)d_in[4];
    const float* bo  = (const float*)d_in[5];
    const float* phi = (const float*)d_in[6];
    float* out = (float*)d_out;

    const int attn_smem = (4096 + 4352 + 4096) * sizeof(float);    // 50176
    const int mma_smem  = 2048 + 3 * 24576;                        // 75776
    cudaFuncSetAttribute(attn_kernel, cudaFuncAttributeMaxDynamicSharedMemorySize, attn_smem);
    cudaFuncSetAttribute(mma_gemm_kernel, cudaFuncAttributeMaxDynamicSharedMemorySize, mma_smem);

    void* alpha_addr = nullptr;
    cudaGetSymbolAddress(&alpha_addr, g_alpha);
    cudaMemsetAsync(alpha_addr, 0, 4 * sizeof(float));

    scales_part_kernel<<<64, 256>>>(Wq, Wk, Wv, Wo);
    scales_fin_kernel<<<1, 32>>>();
    conv_kernel<<<8192, 256>>>(x, Wq, Wk, Wv, Wo);
    mma_gemm_kernel<<<dim3(12, 32), 256, mma_smem>>>(nullptr, phi, nullptr, 0);
    chunksum_kernel<<<dim3(NCH, BH), 256>>>();
    prefix_kernel<<<dim3(5, BH), 256>>>();
    attn_kernel<<<dim3(NCH, BH), 256, attn_smem>>>();
    mma_gemm_kernel<<<dim3(4, 32), 256, mma_smem>>>(bo, nullptr, out, 1);
}

// round 13
// speedup vs baseline: 2.6151x; 1.0204x over previous
#include <cuda_runtime.h>
#include <cuda_bf16.h>
#include <math.h>
#include <stdint.h>

#define DM 512
#define TT 1024
#define BB 2
#define NH 8
#define BH 16      // BB*NH
#define CH 64      // chunk length
#define NCH 16     // TT/CH

// ---------------- scratch (device globals; no allocations) ----------------
__device__ float g_alpha[4];
__device__ int   g_flag[BH*NCH];            // look-back publish flags
__device__ float g_phiQ[BH*TT*64];          // (b,h,t,d)
__device__ float g_phiK[BH*TT*64];
__device__ float g_V  [BH*TT*64];
__device__ float g_kv [BH*NCH*64*64];       // per-chunk K^T V partials
__device__ float g_ks [BH*NCH*64];          // per-chunk K colsum partials
__device__ __nv_bfloat16 g_wt[4*512*512];   // ternary weights in bf16 (exact), [mat][n][k]
__device__ __nv_bfloat16 g_xs[3*2048*512];  // 3-way bf16 split of x
__device__ __nv_bfloat16 g_as[3*2048*512];  // 3-way bf16 split of attention output

// byte-offset swizzle within a 1KB atom (Swizzle<3,4,3>)
#define SWZ(o) ((o) ^ ((((o) >> 7) & 7) << 4))

__device__ __forceinline__ uint32_t smem_u32(const void* p) {
    uint32_t a;
    asm("{ .reg .u64 t; cvta.to.shared.u64 t, %1; cvt.u32.u64 %0, t; }" : "=r"(a) : "l"(p));
    return a;
}
__device__ __forceinline__ void ldmx4(uint32_t* r, uint32_t addr) {
    asm volatile("ldmatrix.sync.aligned.m8n8.x4.shared.b16 {%0,%1,%2,%3}, [%4];"
                 : "=r"(r[0]), "=r"(r[1]), "=r"(r[2]), "=r"(r[3]) : "r"(addr));
}
__device__ __forceinline__ void mma16816(float* c, const uint32_t* a, const uint32_t* b) {
    asm volatile("mma.sync.aligned.m16n8k16.row.col.f32.bf16.bf16.f32 "
                 "{%0,%1,%2,%3},{%4,%5,%6,%7},{%8,%9},{%0,%1,%2,%3};"
                 : "+f"(c[0]), "+f"(c[1]), "+f"(c[2]), "+f"(c[3])
                 : "r"(a[0]), "r"(a[1]), "r"(a[2]), "r"(a[3]), "r"(b[0]), "r"(b[1]));
}
__device__ __forceinline__ int ld_acq(const int* p) {
    int v;
    asm volatile("ld.acquire.gpu.global.s32 %0, [%1];" : "=r"(v) : "l"(p) : "memory");
    return v;
}
__device__ __forceinline__ void st_rel(int* p, int v) {
    asm volatile("st.release.gpu.global.s32 [%0], %1;" :: "l"(p), "r"(v) : "memory");
}
#define CP16(dst, src)  asm volatile("cp.async.cg.shared.global [%0], [%1], 16;" :: "r"(dst), "l"(src))
#define CP_COMMIT()     asm volatile("cp.async.commit_group;" ::: "memory")
#define CP_WAIT1()      asm volatile("cp.async.wait_group 1;" ::: "memory")

// ---------------- 1) ternary scale partial |W| sums ----------------
__global__ void scales_part_kernel(const float* __restrict__ Wq, const float* __restrict__ Wk,
                                   const float* __restrict__ Wv, const float* __restrict__ Wo)
{
    const int mat = blockIdx.x >> 4;             // 16 blocks per matrix
    const float* W = mat==0?Wq: mat==1?Wk: mat==2?Wv:Wo;
    const float4* W4 = (const float4*)(W + (blockIdx.x & 15) * 16384);
    float a = 0.f;
    #pragma unroll 4
    for (int i = threadIdx.x; i < 4096; i += 256) {
        float4 v = W4[i];
        a += fabsf(v.x) + fabsf(v.y) + fabsf(v.z) + fabsf(v.w);
    }
    __shared__ float red[256];
    red[threadIdx.x] = a; __syncthreads();
    for (int o = 128; o > 0; o >>= 1) {
        if (threadIdx.x < o) red[threadIdx.x] += red[threadIdx.x + o];
        __syncthreads();
    }
    if (threadIdx.x == 0) atomicAdd(&g_alpha[mat], red[0]);
}

// ---------------- 2) fused: scales finalize + weights->ternary bf16 + 3-way split of x ----------------
__global__ void conv_kernel(const float* __restrict__ xin,
                            const float* __restrict__ Wq, const float* __restrict__ Wk,
                            const float* __restrict__ Wv, const float* __restrict__ Wo)
{
    int bid = blockIdx.x;
    if (bid < 4096) {
        int i = bid * 256 + threadIdx.x;
        int mat = i >> 18;
        __shared__ float ss, ssi;
        if (threadIdx.x == 0) {
            float alpha = g_alpha[mat] * (1.0f/(DM*DM)) + 1e-12f;
            float e = rintf(log2f(alpha));
            e = fminf(fmaxf(e, -4.f), 4.f);
            ss = exp2f(e); ssi = exp2f(-e);
        }
        __syncthreads();
        const float* W = mat==0?Wq: mat==1?Wk: mat==2?Wv:Wo;
        float v = W[i & 262143];
        float t = fminf(fmaxf(rintf(v * ssi), -1.f), 1.f) * ss;
        g_wt[i] = __float2bfloat16_rn(t);
    } else {
        int i = (bid - 4096) * 256 + threadIdx.x;
        float v = xin[i];
        __nv_bfloat16 h1 = __float2bfloat16_rn(v);
        float r1 = v - __bfloat162float(h1);
        __nv_bfloat16 h2 = __float2bfloat16_rn(r1);
        float r2 = r1 - __bfloat162float(h2);
        g_xs[i] = h1; g_xs[i + 1048576] = h2; g_xs[i + 2097152] = __float2bfloat16_rn(r2);
    }
}

// ---------------- 3) HMMA GEMM, 64x128 tile, cp.async 3-stage, 3 CTAs/SM ----------------
// dyn smem: tbl 2KB @0 | stage s: A 8KB + B 16KB @ 2048 + s*24576   (total 75776 B)
extern __shared__ char DSM[];
__global__ __launch_bounds__(256, 3) void mma_gemm_kernel(
    const float* __restrict__ bias, const float* __restrict__ phi_table,
    float* __restrict__ Out, int mode)
{
    float* tbl = (float*)DSM;
    const uint32_t sbase = smem_u32(DSM);

    const int tid = threadIdx.x;
    const int wid = tid >> 5, lane = tid & 31;
    const int wm = wid >> 2, wn = wid & 3;       // 2 x 4 warp grid; warp tile 32x32

    if (mode == 0) { tbl[tid] = phi_table[tid]; tbl[tid+256] = phi_table[tid+256]; }

    const int m0  = blockIdx.y * 64;
    const int n0g = blockIdx.x * 128;
    const int mat = (mode == 0) ? (n0g >> 9) : 3;
    const int nb0 = (mode == 0) ? (n0g & 511) : n0g;

    const __nv_bfloat16* Aall = (mode == 0) ? g_xs : g_as;
    const __nv_bfloat16* Wbase = g_wt + (size_t)(mat * 512 + nb0) * 512;

    // per-thread cp.async coords: chunks of 16B (A: 2 per thread, B: 4)
    int lrow[4], lcol[4];
    #pragma unroll
    for (int i = 0; i < 4; i++) { int c = i*256 + tid; lrow[i] = c >> 3; lcol[i] = c & 7; }
    uint32_t swoff[4];
    #pragma unroll
    for (int i = 0; i < 4; i++) {
        uint32_t off = (uint32_t)lrow[i] * 128 + lcol[i] * 16;
        swoff[i] = SWZ(off);
    }

    float acc[2][4][4];
    #pragma unroll
    for (int i = 0; i < 2; i++)
        #pragma unroll
        for (int j = 0; j < 4; j++)
            #pragma unroll
            for (int k = 0; k < 4; k++) acc[i][j][k] = 0.f;

    const int t16 = lane & 15;
    uint32_t a_off[2];
    #pragma unroll
    for (int i = 0; i < 2; i++)
        a_off[i] = (uint32_t)(wm*32 + i*16 + t16) * 128 + (lane >> 4) * 16;
    uint32_t b4_off[2];
    #pragma unroll
    for (int j2 = 0; j2 < 2; j2++)
        b4_off[j2] = (uint32_t)(wn*32 + j2*16 + ((lane >> 4) << 3) + (lane & 7)) * 128
                   + (((lane >> 3) & 1) * 16);

    const int NP = 24;                            // 3 splits x 8 k-panels

    auto issue = [&](int p) {
        if (p < NP) {
            int split = p >> 3, kp = (p & 7) * 64;
            const __nv_bfloat16* Ab = Aall + (size_t)split * 1048576 + kp;
            const __nv_bfloat16* Bb = Wbase + kp;
            uint32_t bufA = sbase + 2048 + (uint32_t)(p % 3) * 24576;
            uint32_t bufB = bufA + 8192;
            #pragma unroll
            for (int i = 0; i < 4; i++) {
                if (i < 2)
                    CP16(bufA + swoff[i], Ab + (size_t)(m0 + lrow[i]) * 512 + lcol[i] * 8);
                CP16(bufB + swoff[i], Bb + (size_t)lrow[i] * 512 + lcol[i] * 8);
            }
        }
        CP_COMMIT();
    };

    issue(0); issue(1);

    #pragma unroll 1
    for (int p = 0; p < NP; p++) {
        CP_WAIT1();
        __syncthreads();
        issue(p + 2);

        const uint32_t sA = sbase + 2048 + (uint32_t)(p % 3) * 24576;
        const uint32_t sB = sA + 8192;
        #pragma unroll
        for (int ks = 0; ks < 4; ks++) {
            uint32_t bf[8];
            ldmx4(bf + 0, sB + SWZ(b4_off[0] + ks*32));
            ldmx4(bf + 4, sB + SWZ(b4_off[1] + ks*32));
            #pragma unroll
            for (int i = 0; i < 2; i++) {
                uint32_t af[4];
                ldmx4(af, sA + SWZ(a_off[i] + ks*32));
                #pragma unroll
                for (int j = 0; j < 4; j++)
                    mma16816(acc[i][j], af, bf + j*2);
            }
        }
    }
    __syncthreads();

    // ---------------- epilogue ----------------
    const int lr4 = lane >> 2, lc2 = (lane & 3) * 2;
    if (mode == 0) {
        float* dst = (mat == 0) ? g_phiQ : (mat == 1) ? g_phiK : g_V;
        #pragma unroll
        for (int i = 0; i < 2; i++) {
            #pragma unroll
            for (int half = 0; half < 2; half++) {
                int m = m0 + wm*32 + i*16 + lr4 + half*8;
                int b = m >> 10, t = m & 1023;
                #pragma unroll
                for (int j = 0; j < 4; j++) {
                    int nc = nb0 + wn*32 + j*8 + lc2;
                    float v0 = acc[i][j][half*2+0];
                    float v1 = acc[i][j][half*2+1];
                    if (mat < 2) {
                        int i00 = min(max((int)rintf(__fdiv_rn(v0, 0.1f)) + 128, 0), 255);
                        int i01 = min(max((int)rintf(__fdiv_rn(v0, 0.2f)) + 128, 0), 255);
                        int i10 = min(max((int)rintf(__fdiv_rn(v1, 0.1f)) + 128, 0), 255);
                        int i11 = min(max((int)rintf(__fdiv_rn(v1, 0.2f)) + 128, 0), 255);
                        v0 = tbl[i00] + tbl[256 + i01];
                        v1 = tbl[i10] + tbl[256 + i11];
                    }
                    size_t base = ((size_t)((b << 3) + (nc >> 6)) * 1024 + t) * 64 + (nc & 63);
                    dst[base] = v0;
                    dst[base + 1] = v1;
                }
            }
        }
    } else {
        #pragma unroll
        for (int i = 0; i < 2; i++) {
            #pragma unroll
            for (int half = 0; half < 2; half++) {
                int m = m0 + wm*32 + i*16 + lr4 + half*8;
                #pragma unroll
                for (int j = 0; j < 4; j++) {
                    int n = n0g + wn*32 + j*8 + lc2;
                    Out[(size_t)m * 512 + n]     = acc[i][j][half*2+0] + bias[n];
                    Out[(size_t)m * 512 + n + 1] = acc[i][j][half*2+1] + bias[n+1];
                }
            }
        }
    }
}

// ---------------- 4) FUSED attention: chunk k^T V + decoupled look-back prefix + output ----------------
// dyn smem (floats): Qb[4096] | Kb[64*65=4160] | Vt[64*68=4352] | Sb[4096] | ksb[64]
//   = 16768 floats = 67072 B  -> 3 CTAs/SM, all 256 blocks resident (spin-safe)
__global__ __launch_bounds__(256, 3) void attn_fused_kernel()
{
    float* dsm = (float*)DSM;
    const int chunk = blockIdx.x, bh = blockIdx.y;
    float* Qb  = dsm;
    float* Kb  = dsm + 4096;                     // stride-65 scalar rows (phase 1 + k^T V)
    float* Vt  = dsm + 4096 + 4160;              // stride-17 float4 rows (V, later state)
    float* Sb  = dsm + 4096 + 4160 + 4352;
    float* ksb = dsm + 4096 + 4160 + 4352 + 4096;
    float4* Qb4 = (float4*)Qb;
    float4* Vt4 = (float4*)Vt;
    const int tid = threadIdx.x;
    const int wid = tid >> 5;

    const float* Qg = g_phiQ + (bh*TT + chunk*CH) * 64;
    const float* Kg = g_phiK + (bh*TT + chunk*CH) * 64;
    const float* Vg = g_V    + (bh*TT + chunk*CH) * 64;
    for (int i = tid; i < 1024; i += 256) Qb4[i] = ((const float4*)Qg)[i];
    for (int i = tid; i < 1024; i += 256) {
        int r = i >> 4, cc = (i & 15) << 2;
        float4 v = ((const float4*)Kg)[i];
        Kb[r*65+cc+0]=v.x; Kb[r*65+cc+1]=v.y; Kb[r*65+cc+2]=v.z; Kb[r*65+cc+3]=v.w;
    }
    for (int i = tid; i < 1024; i += 256) {
        int r = i >> 4, c4 = i & 15;
        Vt4[r*17 + c4] = ((const float4*)Vg)[i];
    }
    __syncthreads();

    const int g1 = tid >> 4, g2 = tid & 15;
    const int i0 = g1 * 4;
    const int e4 = g2;

    // ---- step A: this chunk's k^T V partial + colsum -> publish (not needed for last chunk) ----
    if (chunk < NCH-1) {
        const int d0 = (tid >> 4) * 4;
        float pacc[4][4] = {};
        #pragma unroll 4
        for (int t = 0; t < CH; t++) {
            float a0 = Kb[t*65 + d0+0], a1 = Kb[t*65 + d0+1];
            float a2 = Kb[t*65 + d0+2], a3 = Kb[t*65 + d0+3];
            float4 b = Vt4[t*17 + e4];
            pacc[0][0]+=a0*b.x; pacc[0][1]+=a0*b.y; pacc[0][2]+=a0*b.z; pacc[0][3]+=a0*b.w;
            pacc[1][0]+=a1*b.x; pacc[1][1]+=a1*b.y; pacc[1][2]+=a1*b.z; pacc[1][3]+=a1*b.w;
            pacc[2][0]+=a2*b.x; pacc[2][1]+=a2*b.y; pacc[2][2]+=a2*b.z; pacc[2][3]+=a2*b.w;
            pacc[3][0]+=a3*b.x; pacc[3][1]+=a3*b.y; pacc[3][2]+=a3*b.z; pacc[3][3]+=a3*b.w;
        }
        float* kvo = g_kv + ((size_t)bh*NCH + chunk) * 4096;
        #pragma unroll
        for (int r = 0; r < 4; r++)
            *(float4*)(kvo + (d0+r)*64 + e4*4) =
                make_float4(pacc[r][0], pacc[r][1], pacc[r][2], pacc[r][3]);
        if (tid < 64) {
            float su = 0.f;
            for (int t = 0; t < CH; t++) su += Kb[t*65 + tid];
            g_ks[(bh*NCH + chunk)*64 + tid] = su;
        }
        __syncthreads();
        if (tid == 0) { __threadfence(); st_rel(&g_flag[bh*NCH + chunk], 1); }
    }

    // ---- phase 1: S = phiQ @ phiK^T ----
    {
        const int j0 = g2 * 4;
        float sacc[4][4] = {};
        for (int d4 = 0; d4 < 16; d4++) {
            float4 qa0 = Qb4[(i0+0)*16 + d4];
            float4 qa1 = Qb4[(i0+1)*16 + d4];
            float4 qa2 = Qb4[(i0+2)*16 + d4];
            float4 qa3 = Qb4[(i0+3)*16 + d4];
            const float* qp0 = (const float*)&qa0;
            const float* qp1 = (const float*)&qa1;
            const float* qp2 = (const float*)&qa2;
            const float* qp3 = (const float*)&qa3;
            #pragma unroll
            for (int dd = 0; dd < 4; dd++) {
                int d = d4*4 + dd;
                float b0=Kb[(j0+0)*65+d], b1=Kb[(j0+1)*65+d], b2=Kb[(j0+2)*65+d], b3=Kb[(j0+3)*65+d];
                float a0=qp0[dd], a1=qp1[dd], a2=qp2[dd], a3=qp3[dd];
                sacc[0][0]+=a0*b0; sacc[0][1]+=a0*b1; sacc[0][2]+=a0*b2; sacc[0][3]+=a0*b3;
                sacc[1][0]+=a1*b0; sacc[1][1]+=a1*b1; sacc[1][2]+=a1*b2; sacc[1][3]+=a1*b3;
                sacc[2][0]+=a2*b0; sacc[2][1]+=a2*b1; sacc[2][2]+=a2*b2; sacc[2][3]+=a2*b3;
                sacc[3][0]+=a3*b0; sacc[3][1]+=a3*b1; sacc[3][2]+=a3*b2; sacc[3][3]+=a3*b3;
            }
        }
        #pragma unroll
        for (int r = 0; r < 4; r++)
            #pragma unroll
            for (int c = 0; c < 4; c++)
                Sb[(i0+r)*64 + j0+c] = sacc[r][c];
    }
    __syncthreads();

    // ---- phase 2: acc = tril(S) @ V  (causal-truncated per warp; removed terms were exact +0) ----
    float acc[4][4] = {};
    const int jmax = 8*wid + 8;
    for (int j = 0; j < jmax; j++) {
        float4 b = Vt4[j*17 + e4];
        #pragma unroll
        for (int r = 0; r < 4; r++) {
            float sv = (j <= i0 + r) ? Sb[(i0+r)*64 + j] : 0.f;
            acc[r][0]+=sv*b.x; acc[r][1]+=sv*b.y; acc[r][2]+=sv*b.z; acc[r][3]+=sv*b.w;
        }
    }
    __syncthreads();                              // everyone done with Vt as V

    // ---- look-back: state = sum of partials c < chunk (ascending, bit-identical to old prefix) ----
    {
        float4 run0 = make_float4(0,0,0,0), run1 = run0, run2 = run0, run3 = run0;
        float4 runks = make_float4(0,0,0,0);
        for (int c = 0; c < chunk; c++) {
            const int* fl = &g_flag[bh*NCH + c];
            while (ld_acq(fl) == 0) { }
            const float4* kv4 = (const float4*)(g_kv + ((size_t)bh*NCH + c) * 4096);
            float4 t0 = kv4[tid], t1 = kv4[tid+256], t2 = kv4[tid+512], t3 = kv4[tid+768];
            run0.x+=t0.x; run0.y+=t0.y; run0.z+=t0.z; run0.w+=t0.w;
            run1.x+=t1.x; run1.y+=t1.y; run1.z+=t1.z; run1.w+=t1.w;
            run2.x+=t2.x; run2.y+=t2.y; run2.z+=t2.z; run2.w+=t2.w;
            run3.x+=t3.x; run3.y+=t3.y; run3.z+=t3.z; run3.w+=t3.w;
            if (tid < 16) {
                float4 tk = ((const float4*)(g_ks + (bh*NCH + c) * 64))[tid];
                runks.x+=tk.x; runks.y+=tk.y; runks.z+=tk.z; runks.w+=tk.w;
            }
        }
        #pragma unroll
        for (int k = 0; k < 4; k++) {
            int i = tid + k*256;
            float4 v = (k==0)?run0:(k==1)?run1:(k==2)?run2:run3;
            Vt4[(i >> 4)*17 + (i & 15)] = v;
        }
        if (tid < 16) ((float4*)ksb)[tid] = runks;
    }
    __syncthreads();

    // ---- z-pass (threads 0..63) ----
    float zreg = 0.f;
    if (tid < 64) {
        const int i = tid;
        for (int j = 0; j <= i; j++) zreg += Sb[i*64 + j];
        for (int d = 0; d < 64; d++) zreg += Qb[i*64 + d] * ksb[d];
    }
    if (tid < 64) Sb[tid] = zreg;
    __syncthreads();

    // ---- phase 3: acc += phiQ @ state ----
    for (int d4 = 0; d4 < 16; d4++) {
        float4 qa0 = Qb4[(i0+0)*16 + d4];
        float4 qa1 = Qb4[(i0+1)*16 + d4];
        float4 qa2 = Qb4[(i0+2)*16 + d4];
        float4 qa3 = Qb4[(i0+3)*16 + d4];
        const float* qp0 = (const float*)&qa0;
        const float* qp1 = (const float*)&qa1;
        const float* qp2 = (const float*)&qa2;
        const float* qp3 = (const float*)&qa3;
        #pragma unroll
        for (int dd = 0; dd < 4; dd++) {
            float4 b = Vt4[(d4*4+dd)*17 + e4];
            float a0=qp0[dd], a1=qp1[dd], a2=qp2[dd], a3=qp3[dd];
            acc[0][0]+=a0*b.x; acc[0][1]+=a0*b.y; acc[0][2]+=a0*b.z; acc[0][3]+=a0*b.w;
            acc[1][0]+=a1*b.x; acc[1][1]+=a1*b.y; acc[1][2]+=a1*b.z; acc[1][3]+=a1*b.w;
            acc[2][0]+=a2*b.x; acc[2][1]+=a2*b.y; acc[2][2]+=a2*b.z; acc[2][3]+=a2*b.w;
            acc[3][0]+=a3*b.x; acc[3][1]+=a3*b.y; acc[3][2]+=a3*b.z; acc[3][3]+=a3*b.w;
        }
    }

    // ---- epilogue: normalize + exact 3-way bf16 split ----
    const int b = bh >> 3, h = bh & 7;
    const int e0 = g2 * 4;
    #pragma unroll
    for (int r = 0; r < 4; r++) {
        const int t = chunk*CH + i0 + r;
        const float z = fmaxf(Sb[i0 + r], 1e-6f);
        #pragma unroll
        for (int c = 0; c < 4; c++) {
            float o = __fdiv_rn(acc[r][c], z);
            size_t idx = ((size_t)(b*TT + t)) * DM + h*64 + e0 + c;
            __nv_bfloat16 h1 = __float2bfloat16_rn(o);
            float r1 = o - __bfloat162float(h1);
            __nv_bfloat16 h2 = __float2bfloat16_rn(r1);
            float r2 = r1 - __bfloat162float(h2);
            g_as[idx]           = h1;
            g_as[idx + 1048576] = h2;
            g_as[idx + 2097152] = __float2bfloat16_rn(r2);
        }
    }
}

// ---------------- launch ----------------
extern "C" void kernel_launch(void* const* d_in, const int* in_sizes, int n_in,
                              void* d_out, int out_size)
{
    const float* x   = (const float*)d_in[0];
    const float* Wq  = (const float*)d_in[1];
    const float* Wk  = (const float*)d_in[2];
    const float* Wv  = (const float*)d_in[3];
    const float* Wo  = (const float*)d_in[4];
    const float* bo  = (const float*)d_in[5];
    const float* phi = (const float*)d_in[6];
    float* out = (float*)d_out;

    const int attn_smem = 16768 * sizeof(float);                   // 67072
    const int mma_smem  = 2048 + 3 * 24576;                        // 75776
    cudaFuncSetAttribute(attn_fused_kernel, cudaFuncAttributeMaxDynamicSharedMemorySize, attn_smem);
    cudaFuncSetAttribute(mma_gemm_kernel, cudaFuncAttributeMaxDynamicSharedMemorySize, mma_smem);

    void* alpha_addr = nullptr;
    cudaGetSymbolAddress(&alpha_addr, g_alpha);
    cudaMemsetAsync(alpha_addr, 0, 4 * sizeof(float));
    void* flag_addr = nullptr;
    cudaGetSymbolAddress(&flag_addr, g_flag);
    cudaMemsetAsync(flag_addr, 0, BH*NCH * sizeof(int));

    scales_part_kernel<<<64, 256>>>(Wq, Wk, Wv, Wo);
    conv_kernel<<<8192, 256>>>(x, Wq, Wk, Wv, Wo);
    mma_gemm_kernel<<<dim3(12, 32), 256, mma_smem>>>(nullptr, phi, nullptr, 0);
    attn_fused_kernel<<<dim3(NCH, BH), 256, attn_smem>>>();
    mma_gemm_kernel<<<dim3(4, 32), 256, mma_smem>>>(bo, nullptr, out, 1);
}

// round 16
// speedup vs baseline: 2.6523x; 1.0142x over previous
#include <cuda_runtime.h>
#include <cuda_bf16.h>
#include <math.h>
#include <stdint.h>

#define DM 512
#define TT 1024
#define BB 2
#define NH 8
#define BH 16      // BB*NH
#define CH 64      // chunk length
#define NCH 16     // TT/CH

// ---------------- scratch (device globals; no allocations) ----------------
__device__ float g_alpha[4];
__device__ int   g_tflag[384];              // per-QKV-tile publish flags
__device__ int   g_flag[BH*NCH];            // look-back publish flags
__device__ float g_phiQ[BH*TT*64];          // (b,h,t,d)
__device__ float g_phiK[BH*TT*64];
__device__ float g_V  [BH*TT*64];
__device__ float g_kv [BH*NCH*64*64];       // per-chunk K^T V partials
__device__ float g_ks [BH*NCH*64];          // per-chunk K colsum partials
__device__ __nv_bfloat16 g_wt[4*512*512];   // ternary weights in bf16 (exact), [mat][n][k]
__device__ __nv_bfloat16 g_xs[3*2048*512];  // 3-way bf16 split of x
__device__ __nv_bfloat16 g_as[3*2048*512];  // 3-way bf16 split of attention output

// byte-offset swizzle within a 1KB atom (Swizzle<3,4,3>)
#define SWZ(o) ((o) ^ ((((o) >> 7) & 7) << 4))

__device__ __forceinline__ uint32_t smem_u32(const void* p) {
    uint32_t a;
    asm("{ .reg .u64 t; cvta.to.shared.u64 t, %1; cvt.u32.u64 %0, t; }" : "=r"(a) : "l"(p));
    return a;
}
__device__ __forceinline__ void ldmx4(uint32_t* r, uint32_t addr) {
    asm volatile("ldmatrix.sync.aligned.m8n8.x4.shared.b16 {%0,%1,%2,%3}, [%4];"
                 : "=r"(r[0]), "=r"(r[1]), "=r"(r[2]), "=r"(r[3]) : "r"(addr));
}
__device__ __forceinline__ void mma16816(float* c, const uint32_t* a, const uint32_t* b) {
    asm volatile("mma.sync.aligned.m16n8k16.row.col.f32.bf16.bf16.f32 "
                 "{%0,%1,%2,%3},{%4,%5,%6,%7},{%8,%9},{%0,%1,%2,%3};"
                 : "+f"(c[0]), "+f"(c[1]), "+f"(c[2]), "+f"(c[3])
                 : "r"(a[0]), "r"(a[1]), "r"(a[2]), "r"(a[3]), "r"(b[0]), "r"(b[1]));
}
__device__ __forceinline__ int ld_acq(const int* p) {
    int v;
    asm volatile("ld.acquire.gpu.global.s32 %0, [%1];" : "=r"(v) : "l"(p) : "memory");
    return v;
}
__device__ __forceinline__ void st_rel(int* p, int v) {
    asm volatile("st.release.gpu.global.s32 [%0], %1;" :: "l"(p), "r"(v) : "memory");
}
#define CP16(dst, src)  asm volatile("cp.async.cg.shared.global [%0], [%1], 16;" :: "r"(dst), "l"(src))
#define CP_COMMIT()     asm volatile("cp.async.commit_group;" ::: "memory")
#define CP_WAIT1()      asm volatile("cp.async.wait_group 1;" ::: "memory")

// ---------------- 1) ternary scale partial |W| sums ----------------
__global__ void scales_part_kernel(const float* __restrict__ Wq, const float* __restrict__ Wk,
                                   const float* __restrict__ Wv, const float* __restrict__ Wo)
{
    const int mat = blockIdx.x >> 4;             // 16 blocks per matrix
    const float* W = mat==0?Wq: mat==1?Wk: mat==2?Wv:Wo;
    const float4* W4 = (const float4*)(W + (blockIdx.x & 15) * 16384);
    float a = 0.f;
    #pragma unroll 4
    for (int i = threadIdx.x; i < 4096; i += 256) {
        float4 v = W4[i];
        a += fabsf(v.x) + fabsf(v.y) + fabsf(v.z) + fabsf(v.w);
    }
    __shared__ float red[256];
    red[threadIdx.x] = a; __syncthreads();
    for (int o = 128; o > 0; o >>= 1) {
        if (threadIdx.x < o) red[threadIdx.x] += red[threadIdx.x + o];
        __syncthreads();
    }
    if (threadIdx.x == 0) atomicAdd(&g_alpha[mat], red[0]);
}

// ---------------- 2) fused: scales finalize + weights->ternary bf16 + 3-way split of x ----------------
__global__ void conv_kernel(const float* __restrict__ xin,
                            const float* __restrict__ Wq, const float* __restrict__ Wk,
                            const float* __restrict__ Wv, const float* __restrict__ Wo)
{
    int bid = blockIdx.x;
    if (bid < 4096) {
        int i = bid * 256 + threadIdx.x;
        int mat = i >> 18;
        __shared__ float ss, ssi;
        if (threadIdx.x == 0) {
            float alpha = g_alpha[mat] * (1.0f/(DM*DM)) + 1e-12f;
            float e = rintf(log2f(alpha));
            e = fminf(fmaxf(e, -4.f), 4.f);
            ss = exp2f(e); ssi = exp2f(-e);
        }
        __syncthreads();
        const float* W = mat==0?Wq: mat==1?Wk: mat==2?Wv:Wo;
        float v = W[i & 262143];
        float t = fminf(fmaxf(rintf(v * ssi), -1.f), 1.f) * ss;
        g_wt[i] = __float2bfloat16_rn(t);
    } else {
        int i = (bid - 4096) * 256 + threadIdx.x;
        float v = xin[i];
        __nv_bfloat16 h1 = __float2bfloat16_rn(v);
        float r1 = v - __bfloat162float(h1);
        __nv_bfloat16 h2 = __float2bfloat16_rn(r1);
        float r2 = r1 - __bfloat162float(h2);
        g_xs[i] = h1; g_xs[i + 1048576] = h2; g_xs[i + 2097152] = __float2bfloat16_rn(r2);
    }
}

// ---------------- 3) FUSED: QKV HMMA GEMM tile + flag publish + attention unit ----------------
// dyn smem: tbl 2KB @0 | stage s: A 8KB + B 16KB @ 2048 + s*24576  (75776 B total)
// attn phase reuses the same smem as floats: Qb[4096] | Kb[4160] | Vt[4352] | Sb[4096] | ksb[64]
//   = 16768 floats = 67072 B <= 75776 B.
extern __shared__ char DSM[];
__global__ __launch_bounds__(256, 3) void qkv_attn_kernel(const float* __restrict__ phi_table)
{
    float* tbl = (float*)DSM;
    const uint32_t sbase = smem_u32(DSM);
    const int tid = threadIdx.x;
    const int wid = tid >> 5, lane = tid & 31;

    // ======== part 1: QKV GEMM tile ========
    {
        const int bid = blockIdx.x;
        const int bx = bid % 12, by = bid / 12;
        const int wm = wid >> 2, wn = wid & 3;

        tbl[tid] = phi_table[tid]; tbl[tid+256] = phi_table[tid+256];

        const int m0  = by * 64;
        const int n0g = bx * 128;
        const int mat = n0g >> 9;
        const int nb0 = n0g & 511;

        const __nv_bfloat16* Aall = g_xs;
        const __nv_bfloat16* Wbase = g_wt + (size_t)(mat * 512 + nb0) * 512;

        int lrow[4], lcol[4];
        #pragma unroll
        for (int i = 0; i < 4; i++) { int c = i*256 + tid; lrow[i] = c >> 3; lcol[i] = c & 7; }
        uint32_t swoff[4];
        #pragma unroll
        for (int i = 0; i < 4; i++) {
            uint32_t off = (uint32_t)lrow[i] * 128 + lcol[i] * 16;
            swoff[i] = SWZ(off);
        }

        float acc[2][4][4];
        #pragma unroll
        for (int i = 0; i < 2; i++)
            #pragma unroll
            for (int j = 0; j < 4; j++)
                #pragma unroll
                for (int k = 0; k < 4; k++) acc[i][j][k] = 0.f;

        const int t16 = lane & 15;
        uint32_t a_off[2];
        #pragma unroll
        for (int i = 0; i < 2; i++)
            a_off[i] = (uint32_t)(wm*32 + i*16 + t16) * 128 + (lane >> 4) * 16;
        uint32_t b4_off[2];
        #pragma unroll
        for (int j2 = 0; j2 < 2; j2++)
            b4_off[j2] = (uint32_t)(wn*32 + j2*16 + ((lane >> 4) << 3) + (lane & 7)) * 128
                       + (((lane >> 3) & 1) * 16);

        const int NP = 24;

        auto issue = [&](int p) {
            if (p < NP) {
                int split = p >> 3, kp = (p & 7) * 64;
                const __nv_bfloat16* Ab = Aall + (size_t)split * 1048576 + kp;
                const __nv_bfloat16* Bb = Wbase + kp;
                uint32_t bufA = sbase + 2048 + (uint32_t)(p % 3) * 24576;
                uint32_t bufB = bufA + 8192;
                #pragma unroll
                for (int i = 0; i < 4; i++) {
                    if (i < 2)
                        CP16(bufA + swoff[i], Ab + (size_t)(m0 + lrow[i]) * 512 + lcol[i] * 8);
                    CP16(bufB + swoff[i], Bb + (size_t)lrow[i] * 512 + lcol[i] * 8);
                }
            }
            CP_COMMIT();
        };

        issue(0); issue(1);

        #pragma unroll 1
        for (int p = 0; p < NP; p++) {
            CP_WAIT1();
            __syncthreads();
            issue(p + 2);

            const uint32_t sA = sbase + 2048 + (uint32_t)(p % 3) * 24576;
            const uint32_t sB = sA + 8192;
            #pragma unroll
            for (int ks = 0; ks < 4; ks++) {
                uint32_t bf[8];
                ldmx4(bf + 0, sB + SWZ(b4_off[0] + ks*32));
                ldmx4(bf + 4, sB + SWZ(b4_off[1] + ks*32));
                #pragma unroll
                for (int i = 0; i < 2; i++) {
                    uint32_t af[4];
                    ldmx4(af, sA + SWZ(a_off[i] + ks*32));
                    #pragma unroll
                    for (int j = 0; j < 4; j++)
                        mma16816(acc[i][j], af, bf + j*2);
                }
            }
        }
        __syncthreads();

        // epilogue: phi + scatter
        const int lr4 = lane >> 2, lc2 = (lane & 3) * 2;
        float* dst = (mat == 0) ? g_phiQ : (mat == 1) ? g_phiK : g_V;
        #pragma unroll
        for (int i = 0; i < 2; i++) {
            #pragma unroll
            for (int half = 0; half < 2; half++) {
                int m = m0 + wm*32 + i*16 + lr4 + half*8;
                int b = m >> 10, t = m & 1023;
                #pragma unroll
                for (int j = 0; j < 4; j++) {
                    int nc = nb0 + wn*32 + j*8 + lc2;
                    float v0 = acc[i][j][half*2+0];
                    float v1 = acc[i][j][half*2+1];
                    if (mat < 2) {
                        int i00 = min(max((int)rintf(__fdiv_rn(v0, 0.1f)) + 128, 0), 255);
                        int i01 = min(max((int)rintf(__fdiv_rn(v0, 0.2f)) + 128, 0), 255);
                        int i10 = min(max((int)rintf(__fdiv_rn(v1, 0.1f)) + 128, 0), 255);
                        int i11 = min(max((int)rintf(__fdiv_rn(v1, 0.2f)) + 128, 0), 255);
                        v0 = tbl[i00] + tbl[256 + i01];
                        v1 = tbl[i10] + tbl[256 + i11];
                    }
                    size_t base = ((size_t)((b << 3) + (nc >> 6)) * 1024 + t) * 64 + (nc & 63);
                    dst[base] = v0;
                    dst[base + 1] = v1;
                }
            }
        }
        __syncthreads();
        if (tid == 0) { __threadfence(); st_rel(&g_tflag[bid], 1); }
    }

    // ======== part 2: attention unit (blocks 0..255) ========
    if (blockIdx.x >= 256) return;
    const int chunk = blockIdx.x & 15, bh = blockIdx.x >> 4;
    const int b = bh >> 3, h = bh & 7;

    // wait for this unit's 3 producer QKV tiles
    {
        const int by_g = b*16 + chunk;
        const int hx = h >> 1;
        if (tid == 0) {
            while (ld_acq(&g_tflag[by_g*12 + hx]) == 0) { }
            while (ld_acq(&g_tflag[by_g*12 + 4 + hx]) == 0) { }
            while (ld_acq(&g_tflag[by_g*12 + 8 + hx]) == 0) { }
        }
        __syncthreads();
    }

    float* dsm = (float*)DSM;
    float* Qb  = dsm;
    float* Kb  = dsm + 4096;
    float* Vt  = dsm + 4096 + 4160;
    float* Sb  = dsm + 4096 + 4160 + 4352;
    float* ksb = dsm + 4096 + 4160 + 4352 + 4096;
    float4* Qb4 = (float4*)Qb;
    float4* Vt4 = (float4*)Vt;

    const float* Qg = g_phiQ + (bh*TT + chunk*CH) * 64;
    const float* Kg = g_phiK + (bh*TT + chunk*CH) * 64;
    const float* Vg = g_V    + (bh*TT + chunk*CH) * 64;
    for (int i = tid; i < 1024; i += 256) Qb4[i] = ((const float4*)Qg)[i];
    for (int i = tid; i < 1024; i += 256) {
        int r = i >> 4, cc = (i & 15) << 2;
        float4 v = ((const float4*)Kg)[i];
        Kb[r*65+cc+0]=v.x; Kb[r*65+cc+1]=v.y; Kb[r*65+cc+2]=v.z; Kb[r*65+cc+3]=v.w;
    }
    for (int i = tid; i < 1024; i += 256) {
        int r = i >> 4, c4 = i & 15;
        Vt4[r*17 + c4] = ((const float4*)Vg)[i];
    }
    __syncthreads();

    const int g1 = tid >> 4, g2 = tid & 15;
    const int i0 = g1 * 4;
    const int e4 = g2;

    // step A: publish this chunk's k^T V partial + colsum (not needed for last chunk)
    if (chunk < NCH-1) {
        const int d0 = (tid >> 4) * 4;
        float pacc[4][4] = {};
        #pragma unroll 4
        for (int t = 0; t < CH; t++) {
            float a0 = Kb[t*65 + d0+0], a1 = Kb[t*65 + d0+1];
            float a2 = Kb[t*65 + d0+2], a3 = Kb[t*65 + d0+3];
            float4 bb = Vt4[t*17 + e4];
            pacc[0][0]+=a0*bb.x; pacc[0][1]+=a0*bb.y; pacc[0][2]+=a0*bb.z; pacc[0][3]+=a0*bb.w;
            pacc[1][0]+=a1*bb.x; pacc[1][1]+=a1*bb.y; pacc[1][2]+=a1*bb.z; pacc[1][3]+=a1*bb.w;
            pacc[2][0]+=a2*bb.x; pacc[2][1]+=a2*bb.y; pacc[2][2]+=a2*bb.z; pacc[2][3]+=a2*bb.w;
            pacc[3][0]+=a3*bb.x; pacc[3][1]+=a3*bb.y; pacc[3][2]+=a3*bb.z; pacc[3][3]+=a3*bb.w;
        }
        float* kvo = g_kv + ((size_t)bh*NCH + chunk) * 4096;
        #pragma unroll
        for (int r = 0; r < 4; r++)
            *(float4*)(kvo + (d0+r)*64 + e4*4) =
                make_float4(pacc[r][0], pacc[r][1], pacc[r][2], pacc[r][3]);
        if (tid < 64) {
            float su = 0.f;
            for (int t = 0; t < CH; t++) su += Kb[t*65 + tid];
            g_ks[(bh*NCH + chunk)*64 + tid] = su;
        }
        __syncthreads();
        if (tid == 0) { __threadfence(); st_rel(&g_flag[bh*NCH + chunk], 1); }
    }

    // phase 1: S = phiQ @ phiK^T
    {
        const int j0 = g2 * 4;
        float sacc[4][4] = {};
        for (int d4 = 0; d4 < 16; d4++) {
            float4 qa0 = Qb4[(i0+0)*16 + d4];
            float4 qa1 = Qb4[(i0+1)*16 + d4];
            float4 qa2 = Qb4[(i0+2)*16 + d4];
            float4 qa3 = Qb4[(i0+3)*16 + d4];
            const float* qp0 = (const float*)&qa0;
            const float* qp1 = (const float*)&qa1;
            const float* qp2 = (const float*)&qa2;
            const float* qp3 = (const float*)&qa3;
            #pragma unroll
            for (int dd = 0; dd < 4; dd++) {
                int d = d4*4 + dd;
                float b0=Kb[(j0+0)*65+d], b1=Kb[(j0+1)*65+d], b2=Kb[(j0+2)*65+d], b3=Kb[(j0+3)*65+d];
                float a0=qp0[dd], a1=qp1[dd], a2=qp2[dd], a3=qp3[dd];
                sacc[0][0]+=a0*b0; sacc[0][1]+=a0*b1; sacc[0][2]+=a0*b2; sacc[0][3]+=a0*b3;
                sacc[1][0]+=a1*b0; sacc[1][1]+=a1*b1; sacc[1][2]+=a1*b2; sacc[1][3]+=a1*b3;
                sacc[2][0]+=a2*b0; sacc[2][1]+=a2*b1; sacc[2][2]+=a2*b2; sacc[2][3]+=a2*b3;
                sacc[3][0]+=a3*b0; sacc[3][1]+=a3*b1; sacc[3][2]+=a3*b2; sacc[3][3]+=a3*b3;
            }
        }
        #pragma unroll
        for (int r = 0; r < 4; r++)
            #pragma unroll
            for (int c = 0; c < 4; c++)
                Sb[(i0+r)*64 + j0+c] = sacc[r][c];
    }
    __syncthreads();

    // phase 2: acc = tril(S) @ V  (causal-truncated; removed terms were exact +0)
    float acc[4][4] = {};
    const int jmax = 8*wid + 8;
    for (int j = 0; j < jmax; j++) {
        float4 bb = Vt4[j*17 + e4];
        #pragma unroll
        for (int r = 0; r < 4; r++) {
            float sv = (j <= i0 + r) ? Sb[(i0+r)*64 + j] : 0.f;
            acc[r][0]+=sv*bb.x; acc[r][1]+=sv*bb.y; acc[r][2]+=sv*bb.z; acc[r][3]+=sv*bb.w;
        }
    }
    __syncthreads();

    // look-back: state = sum of partials c < chunk (ascending — bit-identical)
    {
        float4 run0 = make_float4(0,0,0,0), run1 = run0, run2 = run0, run3 = run0;
        float4 runks = make_float4(0,0,0,0);
        for (int c = 0; c < chunk; c++) {
            const int* fl = &g_flag[bh*NCH + c];
            while (ld_acq(fl) == 0) { }
            const float4* kv4 = (const float4*)(g_kv + ((size_t)bh*NCH + c) * 4096);
            float4 t0 = kv4[tid], t1 = kv4[tid+256], t2 = kv4[tid+512], t3 = kv4[tid+768];
            run0.x+=t0.x; run0.y+=t0.y; run0.z+=t0.z; run0.w+=t0.w;
            run1.x+=t1.x; run1.y+=t1.y; run1.z+=t1.z; run1.w+=t1.w;
            run2.x+=t2.x; run2.y+=t2.y; run2.z+=t2.z; run2.w+=t2.w;
            run3.x+=t3.x; run3.y+=t3.y; run3.z+=t3.z; run3.w+=t3.w;
            if (tid < 16) {
                float4 tk = ((const float4*)(g_ks + (bh*NCH + c) * 64))[tid];
                runks.x+=tk.x; runks.y+=tk.y; runks.z+=tk.z; runks.w+=tk.w;
            }
        }
        #pragma unroll
        for (int k = 0; k < 4; k++) {
            int i = tid + k*256;
            float4 v = (k==0)?run0:(k==1)?run1:(k==2)?run2:run3;
            Vt4[(i >> 4)*17 + (i & 15)] = v;
        }
        if (tid < 16) ((float4*)ksb)[tid] = runks;
    }
    __syncthreads();

    // z-pass (threads 0..63)
    float zreg = 0.f;
    if (tid < 64) {
        const int i = tid;
        for (int j = 0; j <= i; j++) zreg += Sb[i*64 + j];
        for (int d = 0; d < 64; d++) zreg += Qb[i*64 + d] * ksb[d];
    }
    if (tid < 64) Sb[tid] = zreg;
    __syncthreads();

    // phase 3: acc += phiQ @ state
    for (int d4 = 0; d4 < 16; d4++) {
        float4 qa0 = Qb4[(i0+0)*16 + d4];
        float4 qa1 = Qb4[(i0+1)*16 + d4];
        float4 qa2 = Qb4[(i0+2)*16 + d4];
        float4 qa3 = Qb4[(i0+3)*16 + d4];
        const float* qp0 = (const float*)&qa0;
        const float* qp1 = (const float*)&qa1;
        const float* qp2 = (const float*)&qa2;
        const float* qp3 = (const float*)&qa3;
        #pragma unroll
        for (int dd = 0; dd < 4; dd++) {
            float4 bb = Vt4[(d4*4+dd)*17 + e4];
            float a0=qp0[dd], a1=qp1[dd], a2=qp2[dd], a3=qp3[dd];
            acc[0][0]+=a0*bb.x; acc[0][1]+=a0*bb.y; acc[0][2]+=a0*bb.z; acc[0][3]+=a0*bb.w;
            acc[1][0]+=a1*bb.x; acc[1][1]+=a1*bb.y; acc[1][2]+=a1*bb.z; acc[1][3]+=a1*bb.w;
            acc[2][0]+=a2*bb.x; acc[2][1]+=a2*bb.y; acc[2][2]+=a2*bb.z; acc[2][3]+=a2*bb.w;
            acc[3][0]+=a3*bb.x; acc[3][1]+=a3*bb.y; acc[3][2]+=a3*bb.z; acc[3][3]+=a3*bb.w;
        }
    }

    // epilogue: normalize + exact 3-way bf16 split
    const int e0 = g2 * 4;
    #pragma unroll
    for (int r = 0; r < 4; r++) {
        const int t = chunk*CH + i0 + r;
        const float z = fmaxf(Sb[i0 + r], 1e-6f);
        #pragma unroll
        for (int c = 0; c < 4; c++) {
            float o = __fdiv_rn(acc[r][c], z);
            size_t idx = ((size_t)(b*TT + t)) * DM + h*64 + e0 + c;
            __nv_bfloat16 h1 = __float2bfloat16_rn(o);
            float r1 = o - __bfloat162float(h1);
            __nv_bfloat16 h2 = __float2bfloat16_rn(r1);
            float r2 = r1 - __bfloat162float(h2);
            g_as[idx]           = h1;
            g_as[idx + 1048576] = h2;
            g_as[idx + 2097152] = __float2bfloat16_rn(r2);
        }
    }
}

// ---------------- 4) O-projection HMMA GEMM (64x128 tile, cp.async 3-stage) ----------------
__global__ __launch_bounds__(256, 3) void oproj_kernel(
    const float* __restrict__ bias, float* __restrict__ Out)
{
    const uint32_t sbase = smem_u32(DSM);
    const int tid = threadIdx.x;
    const int wid = tid >> 5, lane = tid & 31;
    const int wm = wid >> 2, wn = wid & 3;

    const int m0  = blockIdx.y * 64;
    const int n0g = blockIdx.x * 128;

    const __nv_bfloat16* Aall = g_as;
    const __nv_bfloat16* Wbase = g_wt + (size_t)(3 * 512 + n0g) * 512;

    int lrow[4], lcol[4];
    #pragma unroll
    for (int i = 0; i < 4; i++) { int c = i*256 + tid; lrow[i] = c >> 3; lcol[i] = c & 7; }
    uint32_t swoff[4];
    #pragma unroll
    for (int i = 0; i < 4; i++) {
        uint32_t off = (uint32_t)lrow[i] * 128 + lcol[i] * 16;
        swoff[i] = SWZ(off);
    }

    float acc[2][4][4];
    #pragma unroll
    for (int i = 0; i < 2; i++)
        #pragma unroll
        for (int j = 0; j < 4; j++)
            #pragma unroll
            for (int k = 0; k < 4; k++) acc[i][j][k] = 0.f;

    const int t16 = lane & 15;
    uint32_t a_off[2];
    #pragma unroll
    for (int i = 0; i < 2; i++)
        a_off[i] = (uint32_t)(wm*32 + i*16 + t16) * 128 + (lane >> 4) * 16;
    uint32_t b4_off[2];
    #pragma unroll
    for (int j2 = 0; j2 < 2; j2++)
        b4_off[j2] = (uint32_t)(wn*32 + j2*16 + ((lane >> 4) << 3) + (lane & 7)) * 128
                   + (((lane >> 3) & 1) * 16);

    const int NP = 24;

    auto issue = [&](int p) {
        if (p < NP) {
            int split = p >> 3, kp = (p & 7) * 64;
            const __nv_bfloat16* Ab = Aall + (size_t)split * 1048576 + kp;
            const __nv_bfloat16* Bb = Wbase + kp;
            uint32_t bufA = sbase + 2048 + (uint32_t)(p % 3) * 24576;
            uint32_t bufB = bufA + 8192;
            #pragma unroll
            for (int i = 0; i < 4; i++) {
                if (i < 2)
                    CP16(bufA + swoff[i], Ab + (size_t)(m0 + lrow[i]) * 512 + lcol[i] * 8);
                CP16(bufB + swoff[i], Bb + (size_t)lrow[i] * 512 + lcol[i] * 8);
            }
        }
        CP_COMMIT();
    };

    issue(0); issue(1);

    #pragma unroll 1
    for (int p = 0; p < NP; p++) {
        CP_WAIT1();
        __syncthreads();
        issue(p + 2);

        const uint32_t sA = sbase + 2048 + (uint32_t)(p % 3) * 24576;
        const uint32_t sB = sA + 8192;
        #pragma unroll
        for (int ks = 0; ks < 4; ks++) {
            uint32_t bf[8];
            ldmx4(bf + 0, sB + SWZ(b4_off[0] + ks*32));
            ldmx4(bf + 4, sB + SWZ(b4_off[1] + ks*32));
            #pragma unroll
            for (int i = 0; i < 2; i++) {
                uint32_t af[4];
                ldmx4(af, sA + SWZ(a_off[i] + ks*32));
                #pragma unroll
                for (int j = 0; j < 4; j++)
                    mma16816(acc[i][j], af, bf + j*2);
            }
        }
    }

    const int lr4 = lane >> 2, lc2 = (lane & 3) * 2;
    #pragma unroll
    for (int i = 0; i < 2; i++) {
        #pragma unroll
        for (int half = 0; half < 2; half++) {
            int m = m0 + wm*32 + i*16 + lr4 + half*8;
            #pragma unroll
            for (int j = 0; j < 4; j++) {
                int n = n0g + wn*32 + j*8 + lc2;
                Out[(size_t)m * 512 + n]     = acc[i][j][half*2+0] + bias[n];
                Out[(size_t)m * 512 + n + 1] = acc[i][j][half*2+1] + bias[n+1];
            }
        }
    }
}

// ---------------- launch ----------------
extern "C" void kernel_launch(void* const* d_in, const int* in_sizes, int n_in,
                              void* d_out, int out_size)
{
    const float* x   = (const float*)d_in[0];
    const float* Wq  = (const float*)d_in[1];
    const float* Wk  = (const float*)d_in[2];
    const float* Wv  = (const float*)d_in[3];
    const float* Wo  = (const float*)d_in[4];
    const float* bo  = (const float*)d_in[5];
    const float* phi = (const float*)d_in[6];
    float* out = (float*)d_out;

    const int mma_smem = 2048 + 3 * 24576;                         // 75776
    cudaFuncSetAttribute(qkv_attn_kernel, cudaFuncAttributeMaxDynamicSharedMemorySize, mma_smem);
    cudaFuncSetAttribute(oproj_kernel, cudaFuncAttributeMaxDynamicSharedMemorySize, mma_smem);

    void* alpha_addr = nullptr;
    cudaGetSymbolAddress(&alpha_addr, g_alpha);
    cudaMemsetAsync(alpha_addr, 0, 4 * sizeof(float));
    void* tflag_addr = nullptr;
    cudaGetSymbolAddress(&tflag_addr, g_tflag);
    cudaMemsetAsync(tflag_addr, 0, 384 * sizeof(int));
    void* flag_addr = nullptr;
    cudaGetSymbolAddress(&flag_addr, g_flag);
    cudaMemsetAsync(flag_addr, 0, BH*NCH * sizeof(int));

    scales_part_kernel<<<64, 256>>>(Wq, Wk, Wv, Wo);
    conv_kernel<<<8192, 256>>>(x, Wq, Wk, Wv, Wo);
    qkv_attn_kernel<<<384, 256, mma_smem>>>(phi);
    oproj_kernel<<<dim3(4, 32), 256, mma_smem>>>(bo, out);
}